// round 3
// baseline (speedup 1.0000x reference)
#include <cuda_runtime.h>

#define G 64
#define S (G*G*G)          // 262144 cells
#define L 64
#define NPTS 150000

typedef unsigned long long ull;

// ---------------- packed f32x2 helpers (Blackwell FFMA2 path) ---------------
__device__ __forceinline__ ull pack2(float x, float y) {
    ull r;
    asm("mov.b64 %0, {%1, %2};" : "=l"(r) : "r"(__float_as_uint(x)), "r"(__float_as_uint(y)));
    return r;
}
__device__ __forceinline__ ull pack_dup(float x) {
    ull r;
    asm("mov.b64 %0, {%1, %1};" : "=l"(r) : "r"(__float_as_uint(x)));
    return r;
}
__device__ __forceinline__ void fma2(ull& d, ull a, ull b) {
    asm("fma.rn.f32x2 %0, %1, %2, %0;" : "+l"(d) : "l"(a), "l"(b));
}
__device__ __forceinline__ float2 unpack2(ull v) {
    unsigned lo, hi;
    asm("mov.b64 {%0, %1}, %2;" : "=r"(lo), "=r"(hi) : "l"(v));
    return make_float2(__uint_as_float(lo), __uint_as_float(hi));
}

// ---------------- scratch (device globals; no allocation allowed) ----------
__device__ float g_sums[S*L];        // 67 MB: scatter sums -> normalized grid
__device__ float g_cnt[S];           // 1 MB
__device__ float g_mid[S*L];         // 67 MB: conv1 output
__device__ float g_wp1[27*L*L];      // conv1 weights repacked [tap][i][o]
__device__ float g_wp2[27*L*L];

// ---------------- weight repack: (O,I,3,3,3) -> [t][i][o] -------------------
__global__ void repack_w(const float* __restrict__ cw, float* __restrict__ dst) {
    int idx = blockIdx.x * 256 + threadIdx.x;
    if (idx < 27*64*64) {
        int t = idx >> 12;          // tap
        int r = idx & 4095;
        int i = r >> 6, o = r & 63;
        dst[idx] = cw[(o*64 + i)*27 + t];
    }
}

// ---------------- fused point MLP + atomic scatter --------------------------
__global__ __launch_bounds__(256) void mlp_scatter(
    const float* __restrict__ pos, const int* __restrict__ pts,
    const float* __restrict__ W1, const float* __restrict__ b1,
    const float* __restrict__ W2, const float* __restrict__ b2,
    const float* __restrict__ Wk1, const float* __restrict__ bk1,
    const float* __restrict__ Wk2, const float* __restrict__ bk2)
{
    __shared__ float W2s[64*64];
    __shared__ float W1s[192], b1s[64], b2s[64], Wk1s[64], bk1s[8], Wk2s[8], bk2s[1];
    __shared__ __align__(16) float h_s[4][512];   // 4 point-groups x (8k x 64l)
    __shared__ float pos_s[4][24];
    __shared__ int   cell_s[4];

    int tid = threadIdx.x;
    for (int i = tid; i < 4096; i += 256) W2s[i] = W2[i];
    if (tid < 192) W1s[tid] = W1[tid];
    if (tid < 64) { b1s[tid] = b1[tid]; b2s[tid] = b2[tid]; Wk1s[tid] = Wk1[tid]; }
    if (tid < 8)  { bk1s[tid] = bk1[tid]; Wk2s[tid] = Wk2[tid]; }
    if (tid == 0) bk2s[0] = bk2[0];
    __syncthreads();

    int grp = tid >> 6, l = tid & 63;
    for (int base = blockIdx.x * 4; base < NPTS; base += gridDim.x * 4) {
        int p = base + grp;
        bool valid = p < NPTS;
        if (valid && l < 24) pos_s[grp][l] = pos[p*24 + l];
        if (valid && l == 0)
            cell_s[grp] = (pts[p*3]*G + pts[p*3+1])*G + pts[p*3+2];
        __syncthreads();

        // h[k][l] = lrelu(pos . W1 + b1)
        #pragma unroll
        for (int k = 0; k < 8; ++k) {
            float v = pos_s[grp][k*3+0]*W1s[l] + pos_s[grp][k*3+1]*W1s[64+l]
                    + pos_s[grp][k*3+2]*W1s[128+l] + b1s[l];
            h_s[grp][k*64 + l] = v >= 0.f ? v : 0.01f*v;
        }
        __syncthreads();

        // feat[k][l] = h[k] @ W2 + b2   -- packed f32x2: j-parity partial sums
        ull acc2[8];
        #pragma unroll
        for (int k = 0; k < 8; ++k) acc2[k] = pack2(b2s[l], 0.f);
        #pragma unroll 8
        for (int j = 0; j < 64; j += 2) {
            ull bb = pack2(W2s[j*64 + l], W2s[(j+1)*64 + l]);
            #pragma unroll
            for (int k = 0; k < 8; ++k) {
                ull hv = *(const ull*)&h_s[grp][k*64 + j];  // (h[j], h[j+1]), 8B aligned
                fma2(acc2[k], hv, bb);
            }
        }
        float acc[8];
        #pragma unroll
        for (int k = 0; k < 8; ++k) {
            float2 pxy = unpack2(acc2[k]);
            acc[k] = pxy.x + pxy.y;
        }

        // f1 = lrelu(Wk1 @ feat + bk1); f2 = Wk2 @ f1 + bk2
        float f1[8];
        #pragma unroll
        for (int o = 0; o < 8; ++o) {
            float s = bk1s[o];
            #pragma unroll
            for (int k = 0; k < 8; ++k) s += Wk1s[o*8 + k] * acc[k];
            f1[o] = s >= 0.f ? s : 0.01f*s;
        }
        float f2 = bk2s[0];
        #pragma unroll
        for (int o = 0; o < 8; ++o) f2 += Wk2s[o] * f1[o];

        if (valid) {
            int cell = cell_s[grp];
            atomicAdd(&g_sums[cell*64 + l], f2);
            if (l == 0) atomicAdd(&g_cnt[cell], 1.0f);
        }
        __syncthreads();
    }
}

// ---------------- normalize: grid = sums / max(cnt,1), 0 where empty --------
__global__ void normalize_k() {
    int idx = blockIdx.x * 256 + threadIdx.x;   // over 4,194,304 float4s
    float c = g_cnt[idx >> 4];                  // 16 float4 per cell
    float inv = c > 0.f ? 1.f / c : 0.f;
    float4 v = ((float4*)g_sums)[idx];
    v.x *= inv; v.y *= inv; v.z *= inv; v.w *= inv;
    ((float4*)g_sums)[idx] = v;
}

// ---------------- conv3d 64->64ch, 3x3x3, pad 1, + bias, ReLU ---------------
// block = one (d,h) row (64 w) x 64 out-channels; 128 threads.
// thread tile: 4 w x 8 o, accumulated as packed f32x2 o-pairs (FFMA2 path).
__global__ __launch_bounds__(128) void conv3d_k(
    const float* __restrict__ x, float* __restrict__ y,
    const float* __restrict__ wt /* [27][64i][64o] */,
    const float* __restrict__ bias)
{
    __shared__ __align__(16) float As[64*67];   // [i][w+1], stride 67 (conflict-free)
    __shared__ __align__(16) float Bs[64*64];   // [i][o] for current tap
    int tid = threadIdx.x;
    int bh = blockIdx.x & 63, bd = blockIdx.x >> 6;
    int to = tid & 7;     // o tile: o = to*8 .. to*8+7
    int tw = tid >> 3;    // w tile: w = tw*4 .. tw*4+3

    ull acc[4][4];        // [m = w offset][op = o pair]  -> 16 x b64
    #pragma unroll
    for (int m = 0; m < 4; ++m)
        #pragma unroll
        for (int op = 0; op < 4; ++op) acc[m][op] = 0ull;

    for (int dzy = 0; dzy < 9; ++dzy) {
        int dd = bd + dzy/3 - 1;
        int hh = bh + dzy%3 - 1;
        if ((unsigned)dd >= (unsigned)G || (unsigned)hh >= (unsigned)G) continue;
        const float* xrow = x + (size_t)((dd*G + hh)*G) * 64;

        __syncthreads();   // prior GEMM done before overwriting As
        // transpose-load row: As[i][w+1] = xrow[w][i]; vectorized over i
        for (int idx4 = tid; idx4 < 1024; idx4 += 128) {
            int w = idx4 >> 4, i0 = (idx4 & 15) * 4;
            float4 v = ((const float4*)xrow)[idx4];
            As[(i0+0)*67 + w + 1] = v.x;
            As[(i0+1)*67 + w + 1] = v.y;
            As[(i0+2)*67 + w + 1] = v.z;
            As[(i0+3)*67 + w + 1] = v.w;
        }
        if (tid < 64) { As[tid*67] = 0.f; As[tid*67 + 65] = 0.f; }  // w padding

        for (int dx = 0; dx < 3; ++dx) {
            __syncthreads();   // prior GEMM done before overwriting Bs (also: As ready)
            const float4* wsrc = (const float4*)(wt + (dzy*3 + dx)*4096);
            for (int idx4 = tid; idx4 < 1024; idx4 += 128)
                ((float4*)Bs)[idx4] = wsrc[idx4];
            __syncthreads();

            const float* ap = As + tw*4 + dx;   // As index = i*67 + (w + dx)
            const float* bp = Bs + to*8;
            #pragma unroll 4
            for (int i = 0; i < 64; ++i) {
                ulonglong2 b01 = *(const ulonglong2*)(bp + i*64);      // o pairs {0,1},{2,3}
                ulonglong2 b23 = *(const ulonglong2*)(bp + i*64 + 4);  // o pairs {4,5},{6,7}
                #pragma unroll
                for (int m = 0; m < 4; ++m) {
                    ull aa = pack_dup(ap[i*67 + m]);
                    fma2(acc[m][0], aa, b01.x);
                    fma2(acc[m][1], aa, b01.y);
                    fma2(acc[m][2], aa, b23.x);
                    fma2(acc[m][3], aa, b23.y);
                }
            }
        }
    }

    float4 bb0 = *(const float4*)&bias[to*8];
    float4 bb1 = *(const float4*)&bias[to*8 + 4];
    int sbase = (bd*G + bh)*G;
    #pragma unroll
    for (int m = 0; m < 4; ++m) {
        int w = tw*4 + m;
        float2 p0 = unpack2(acc[m][0]);
        float2 p1 = unpack2(acc[m][1]);
        float2 p2 = unpack2(acc[m][2]);
        float2 p3 = unpack2(acc[m][3]);
        float4 r0, r1;
        r0.x = fmaxf(p0.x + bb0.x, 0.f);
        r0.y = fmaxf(p0.y + bb0.y, 0.f);
        r0.z = fmaxf(p1.x + bb0.z, 0.f);
        r0.w = fmaxf(p1.y + bb0.w, 0.f);
        r1.x = fmaxf(p2.x + bb1.x, 0.f);
        r1.y = fmaxf(p2.y + bb1.y, 0.f);
        r1.z = fmaxf(p3.x + bb1.z, 0.f);
        r1.w = fmaxf(p3.y + bb1.w, 0.f);
        float* dst = &y[(size_t)(sbase + w)*64 + to*8];
        *(float4*)dst       = r0;
        *(float4*)(dst + 4) = r1;
    }
}

// ---------------- launch -----------------------------------------------------
extern "C" void kernel_launch(void* const* d_in, const int* in_sizes, int n_in,
                              void* d_out, int out_size)
{
    const float* pos = (const float*)d_in[0];
    const int*   pts = (const int*)d_in[1];
    const float* W1  = (const float*)d_in[2];
    const float* b1  = (const float*)d_in[3];
    const float* W2  = (const float*)d_in[4];
    const float* b2  = (const float*)d_in[5];
    const float* Wk1 = (const float*)d_in[6];
    const float* bk1 = (const float*)d_in[7];
    const float* Wk2 = (const float*)d_in[8];
    const float* bk2 = (const float*)d_in[9];
    const float* Cw1 = (const float*)d_in[10];
    const float* Cb1 = (const float*)d_in[11];
    const float* Cw2 = (const float*)d_in[12];
    const float* Cb2 = (const float*)d_in[13];
    float* out = (float*)d_out;

    void *pSums, *pCnt, *pMid, *pW1, *pW2;
    cudaGetSymbolAddress(&pSums, g_sums);
    cudaGetSymbolAddress(&pCnt,  g_cnt);
    cudaGetSymbolAddress(&pMid,  g_mid);
    cudaGetSymbolAddress(&pW1,   g_wp1);
    cudaGetSymbolAddress(&pW2,   g_wp2);

    cudaMemsetAsync(pSums, 0, sizeof(float) * (size_t)S * L);
    cudaMemsetAsync(pCnt,  0, sizeof(float) * (size_t)S);

    repack_w<<<432, 256>>>(Cw1, (float*)pW1);
    repack_w<<<432, 256>>>(Cw2, (float*)pW2);

    mlp_scatter<<<2368, 256>>>(pos, pts, W1, b1, W2, b2, Wk1, bk1, Wk2, bk2);
    normalize_k<<<16384, 256>>>();

    conv3d_k<<<G*G, 128>>>((const float*)pSums, (float*)pMid, (const float*)pW1, Cb1);
    conv3d_k<<<G*G, 128>>>((const float*)pMid,  out,          (const float*)pW2, Cb2);
}

// round 5
// speedup vs baseline: 2.8393x; 2.8393x over previous
#include <cuda_runtime.h>
#include <cuda_bf16.h>

#define G 64
#define S (G*G*G)
#define L 64
#define NPTS 150000
#define PADW 72                      // padded row stride (144B): ldmatrix conflict-free

// ---------------- scratch (device globals; no allocation allowed) ----------
__device__ float g_sums[S*L];                                  // 67 MB
__device__ float g_cnt[S];                                     // 1 MB
__device__ __align__(16) __nv_bfloat16 g_xh[S*L], g_xl[S*L];   // conv1 input hi/lo
__device__ __align__(16) __nv_bfloat16 g_yh[S*L], g_yl[S*L];   // conv1 out hi/lo
__device__ __align__(16) __nv_bfloat16 g_w1h[27*L*L], g_w1l[27*L*L];  // [t][o][i]
__device__ __align__(16) __nv_bfloat16 g_w2h[27*L*L], g_w2l[27*L*L];

__device__ __forceinline__ unsigned pack_bf2(__nv_bfloat16 a, __nv_bfloat16 b) {
    return ((unsigned)__bfloat16_as_ushort(b) << 16) | (unsigned)__bfloat16_as_ushort(a);
}

__device__ __forceinline__ void ldsm4(unsigned addr, unsigned& r0, unsigned& r1,
                                      unsigned& r2, unsigned& r3) {
    asm volatile("ldmatrix.sync.aligned.m8n8.x4.shared.b16 {%0,%1,%2,%3}, [%4];"
        : "=r"(r0), "=r"(r1), "=r"(r2), "=r"(r3) : "r"(addr));
}
__device__ __forceinline__ void mma16816(float* c, const unsigned* a,
                                         unsigned b0, unsigned b1) {
    asm volatile("mma.sync.aligned.m16n8k16.row.col.f32.bf16.bf16.f32 "
        "{%0,%1,%2,%3}, {%4,%5,%6,%7}, {%8,%9}, {%0,%1,%2,%3};"
        : "+f"(c[0]), "+f"(c[1]), "+f"(c[2]), "+f"(c[3])
        : "r"(a[0]), "r"(a[1]), "r"(a[2]), "r"(a[3]), "r"(b0), "r"(b1));
}

// ---------------- weight repack + split: (O,I,3,3,3) -> [t][o][i] hi/lo ------
__global__ void repack_split(const float* __restrict__ cw,
                             __nv_bfloat16* __restrict__ wh,
                             __nv_bfloat16* __restrict__ wl) {
    int idx = blockIdx.x * 256 + threadIdx.x;
    if (idx >= 27*64*64) return;
    int t = idx >> 12, r = idx & 4095;
    int o = r >> 6, i = r & 63;
    float v = cw[(o*64 + i)*27 + t];
    __nv_bfloat16 h = __float2bfloat16(v);
    wh[idx] = h;
    wl[idx] = __float2bfloat16(v - __bfloat162float(h));
}

// ---------------- fused point MLP + atomic scatter (R1 scalar, proven) ------
__global__ __launch_bounds__(256) void mlp_scatter(
    const float* __restrict__ pos, const int* __restrict__ pts,
    const float* __restrict__ W1, const float* __restrict__ b1,
    const float* __restrict__ W2, const float* __restrict__ b2,
    const float* __restrict__ Wk1, const float* __restrict__ bk1,
    const float* __restrict__ Wk2, const float* __restrict__ bk2)
{
    __shared__ float W2s[64*64];
    __shared__ float W1s[192], b1s[64], b2s[64], Wk1s[64], bk1s[8], Wk2s[8], bk2s[1];
    __shared__ __align__(16) float h_s[4][512];
    __shared__ float pos_s[4][24];
    __shared__ int   cell_s[4];

    int tid = threadIdx.x;
    for (int i = tid; i < 4096; i += 256) W2s[i] = W2[i];
    if (tid < 192) W1s[tid] = W1[tid];
    if (tid < 64) { b1s[tid] = b1[tid]; b2s[tid] = b2[tid]; Wk1s[tid] = Wk1[tid]; }
    if (tid < 8)  { bk1s[tid] = bk1[tid]; Wk2s[tid] = Wk2[tid]; }
    if (tid == 0) bk2s[0] = bk2[0];
    __syncthreads();

    int grp = tid >> 6, l = tid & 63;
    for (int base = blockIdx.x * 4; base < NPTS; base += gridDim.x * 4) {
        int p = base + grp;
        bool valid = p < NPTS;
        if (valid && l < 24) pos_s[grp][l] = pos[p*24 + l];
        if (valid && l == 0)
            cell_s[grp] = (pts[p*3]*G + pts[p*3+1])*G + pts[p*3+2];
        __syncthreads();

        #pragma unroll
        for (int k = 0; k < 8; ++k) {
            float v = pos_s[grp][k*3+0]*W1s[l] + pos_s[grp][k*3+1]*W1s[64+l]
                    + pos_s[grp][k*3+2]*W1s[128+l] + b1s[l];
            h_s[grp][k*64 + l] = v >= 0.f ? v : 0.01f*v;
        }
        __syncthreads();

        float acc[8];
        #pragma unroll
        for (int k = 0; k < 8; ++k) acc[k] = b2s[l];
        #pragma unroll 4
        for (int j = 0; j < 64; j += 4) {
            float w0 = W2s[(j+0)*64+l], w1 = W2s[(j+1)*64+l];
            float w2 = W2s[(j+2)*64+l], w3 = W2s[(j+3)*64+l];
            #pragma unroll
            for (int k = 0; k < 8; ++k) {
                float4 hv = *(const float4*)&h_s[grp][k*64 + j];
                acc[k] += hv.x*w0 + hv.y*w1 + hv.z*w2 + hv.w*w3;
            }
        }

        float f1[8];
        #pragma unroll
        for (int o = 0; o < 8; ++o) {
            float s = bk1s[o];
            #pragma unroll
            for (int k = 0; k < 8; ++k) s += Wk1s[o*8 + k] * acc[k];
            f1[o] = s >= 0.f ? s : 0.01f*s;
        }
        float f2 = bk2s[0];
        #pragma unroll
        for (int o = 0; o < 8; ++o) f2 += Wk2s[o] * f1[o];

        if (valid) {
            int cell = cell_s[grp];
            atomicAdd(&g_sums[cell*64 + l], f2);
            if (l == 0) atomicAdd(&g_cnt[cell], 1.0f);
        }
        __syncthreads();
    }
}

// ---------------- normalize + bf16 hi/lo split -------------------------------
__global__ void normalize_split() {
    int idx = blockIdx.x * 256 + threadIdx.x;   // S*16 float4 groups
    float c = g_cnt[idx >> 4];
    float inv = c > 0.f ? 1.f / c : 0.f;
    float4 v = ((const float4*)g_sums)[idx];
    v.x *= inv; v.y *= inv; v.z *= inv; v.w *= inv;
    __nv_bfloat16 h0 = __float2bfloat16(v.x), h1 = __float2bfloat16(v.y);
    __nv_bfloat16 h2 = __float2bfloat16(v.z), h3 = __float2bfloat16(v.w);
    __nv_bfloat16 l0 = __float2bfloat16(v.x - __bfloat162float(h0));
    __nv_bfloat16 l1 = __float2bfloat16(v.y - __bfloat162float(h1));
    __nv_bfloat16 l2 = __float2bfloat16(v.z - __bfloat162float(h2));
    __nv_bfloat16 l3 = __float2bfloat16(v.w - __bfloat162float(h3));
    ((uint2*)g_xh)[idx] = make_uint2(pack_bf2(h0,h1), pack_bf2(h2,h3));
    ((uint2*)g_xl)[idx] = make_uint2(pack_bf2(l0,l1), pack_bf2(l2,l3));
}

// ---------------- mma.sync conv3d 64->64ch 3x3x3 pad1 + bias + ReLU ---------
// CTA: 2 h-rows x 64 w (M=128) x 64 out-ch (N=64). 8 warps, warp tile 32x32.
// bf16 hi/lo 3-term split on the tensor pipe; fp32 accumulate in registers.
// A smem [hl][hrow][w-slot 0..65][c], stride PADW: dx shift = pointer offset.
#define A_ELEMS (2*2*66*PADW)            // 19008
#define W_ELEMS (2*64*PADW)              // 9216
#define CONV_SMEM ((A_ELEMS + W_ELEMS) * 2)   // 56448 bytes

template<bool SPLIT_OUT>
__global__ void __launch_bounds__(256) conv_mma(
    const __nv_bfloat16* __restrict__ xh, const __nv_bfloat16* __restrict__ xl,
    const __nv_bfloat16* __restrict__ wth, const __nv_bfloat16* __restrict__ wtl,
    const float* __restrict__ bias,
    float* __restrict__ outF,
    __nv_bfloat16* __restrict__ outH, __nv_bfloat16* __restrict__ outL)
{
    extern __shared__ __align__(16) char sm_raw[];
    __nv_bfloat16* smA = (__nv_bfloat16*)sm_raw;                 // [hl][hrow][66][PADW]
    __nv_bfloat16* smW = (__nv_bfloat16*)(sm_raw + A_ELEMS*2);   // [hl][o][PADW]
    const unsigned Abase = (unsigned)__cvta_generic_to_shared(smA);
    const unsigned Wbase = (unsigned)__cvta_generic_to_shared(smW);

    const int tid = threadIdx.x;
    const int wid = tid >> 5, lane = tid & 31;
    const int d0 = blockIdx.x >> 5;
    const int h0 = (blockIdx.x & 31) << 1;
    const int warp_m = wid & 3, warp_n = wid >> 2;   // m0 = warp_m*32, n0 = warp_n*32

    // ---- per-lane ldmatrix address components ----
    const int t8 = lane >> 3, lr = lane & 7;
    // A fragments: [hl][mb] byte offsets (add dx*144 + k0*2 at use)
    unsigned aOff[2][2];
    #pragma unroll
    for (int hl = 0; hl < 2; ++hl)
        #pragma unroll
        for (int mb = 0; mb < 2; ++mb) {
            int r = warp_m*32 + mb*16 + (t8 & 1)*8 + lr;   // 0..127
            int hrow = r >> 6, w = r & 63;
            aOff[hl][mb] = (unsigned)((((hl*2 + hrow)*66 + w)*PADW + (t8 >> 1)*8) * 2);
        }
    // B fragments: [hl][pair] byte offsets (add k0*2)
    unsigned bOff[2][2];
    #pragma unroll
    for (int hl = 0; hl < 2; ++hl)
        #pragma unroll
        for (int pr = 0; pr < 2; ++pr) {
            int n = warp_n*32 + pr*16 + (t8 >> 1)*8 + lr;
            bOff[hl][pr] = (unsigned)(((hl*64 + n)*PADW + (t8 & 1)*8) * 2);
        }

    float acc[2][4][4];
    #pragma unroll
    for (int mb = 0; mb < 2; ++mb)
        #pragma unroll
        for (int nb = 0; nb < 4; ++nb)
            #pragma unroll
            for (int q = 0; q < 4; ++q) acc[mb][nb][q] = 0.f;

    // A-load role: group g = tid>>6 handles (hl = g>>1, hrow = g&1); thread w = tid&63
    const int gA = tid >> 6, hlA = gA >> 1, hrA = gA & 1, wA = tid & 63;
    __nv_bfloat16* dstA = smA + ((hlA*2 + hrA)*66 + (wA + 1))*PADW;
    const __nv_bfloat16* srcA_base = hlA ? xl : xh;

    for (int dzy = 0; dzy < 9; ++dzy) {
        const int dz = dzy / 3, dy = dzy % 3;
        const int dd = d0 + dz - 1;
        if ((unsigned)dd >= (unsigned)G) continue;   // uniform per CTA

        __syncthreads();   // prior tap's compute done before overwriting A
        {
            const int hin = h0 + dy - 1 + hrA;
            float4* d4 = (float4*)dstA;
            if ((unsigned)hin < (unsigned)G) {
                const float4* s4 = (const float4*)(srcA_base +
                    (((size_t)(dd*G + hin))*G + wA) * 64);
                #pragma unroll
                for (int j = 0; j < 8; ++j) d4[j] = s4[j];
            } else {
                float4 z = make_float4(0.f, 0.f, 0.f, 0.f);
                #pragma unroll
                for (int j = 0; j < 8; ++j) d4[j] = z;
            }
            if (wA == 0) {      // halo slot 0
                float4 z = make_float4(0.f, 0.f, 0.f, 0.f);
                float4* h4 = (float4*)(smA + ((hlA*2 + hrA)*66)*PADW);
                #pragma unroll
                for (int j = 0; j < 8; ++j) h4[j] = z;
            }
            if (wA == 63) {     // halo slot 65
                float4 z = make_float4(0.f, 0.f, 0.f, 0.f);
                float4* h4 = (float4*)(smA + ((hlA*2 + hrA)*66 + 65)*PADW);
                #pragma unroll
                for (int j = 0; j < 8; ++j) h4[j] = z;
            }
        }

        for (int dx = 0; dx < 3; ++dx) {
            const int tap = dzy*3 + dx;
            __syncthreads();   // prior compute done before overwriting W (and A ready)
            // load W tap: 128 rows (2 hl x 64 o) x 64 i, as 8-elem chunks
            for (int idx = tid; idx < 1024; idx += 256) {
                int row = idx >> 3, cch = idx & 7;
                int hl = row >> 6, o = row & 63;
                const __nv_bfloat16* s = (hl ? wtl : wth) + ((size_t)tap*4096 + o*64 + cch*8);
                *(float4*)(smW + (hl*64 + o)*PADW + cch*8) = *(const float4*)s;
            }
            __syncthreads();

            const unsigned Adx = Abase + (unsigned)(dx * PADW * 2);
            #pragma unroll
            for (int k0 = 0; k0 < 64; k0 += 16) {
                unsigned ah[2][4], al[2][4], bh[2][4], bl[2][4];
                #pragma unroll
                for (int mb = 0; mb < 2; ++mb) {
                    ldsm4(Adx + aOff[0][mb] + k0*2, ah[mb][0], ah[mb][1], ah[mb][2], ah[mb][3]);
                    ldsm4(Adx + aOff[1][mb] + k0*2, al[mb][0], al[mb][1], al[mb][2], al[mb][3]);
                }
                #pragma unroll
                for (int pr = 0; pr < 2; ++pr) {
                    ldsm4(Wbase + bOff[0][pr] + k0*2, bh[pr][0], bh[pr][1], bh[pr][2], bh[pr][3]);
                    ldsm4(Wbase + bOff[1][pr] + k0*2, bl[pr][0], bl[pr][1], bl[pr][2], bl[pr][3]);
                }
                #pragma unroll
                for (int mb = 0; mb < 2; ++mb)
                    #pragma unroll
                    for (int nb = 0; nb < 4; ++nb) {
                        int pr = nb >> 1, sel = (nb & 1) << 1;   // regs {sel, sel+1}
                        mma16816(acc[mb][nb], ah[mb], bh[pr][sel], bh[pr][sel+1]);
                        mma16816(acc[mb][nb], ah[mb], bl[pr][sel], bl[pr][sel+1]);
                        mma16816(acc[mb][nb], al[mb], bh[pr][sel], bh[pr][sel+1]);
                    }
            }
        }
    }

    // ---- epilogue: bias + ReLU, write out ----
    const int gid = lane >> 2, qid = lane & 3;
    #pragma unroll
    for (int mb = 0; mb < 2; ++mb)
        #pragma unroll
        for (int nb = 0; nb < 4; ++nb) {
            int n = warp_n*32 + nb*8 + qid*2;
            float2 bb = *(const float2*)&bias[n];
            #pragma unroll
            for (int half = 0; half < 2; ++half) {
                int m = warp_m*32 + mb*16 + gid + half*8;
                int hrow = m >> 6, w = m & 63;
                size_t pos = ((size_t)((d0*G + h0 + hrow)*G + w))*64 + n;
                float v0 = fmaxf(acc[mb][nb][half*2+0] + bb.x, 0.f);
                float v1 = fmaxf(acc[mb][nb][half*2+1] + bb.y, 0.f);
                if (SPLIT_OUT) {
                    __nv_bfloat16 a0 = __float2bfloat16(v0), a1 = __float2bfloat16(v1);
                    __nv_bfloat16 c0 = __float2bfloat16(v0 - __bfloat162float(a0));
                    __nv_bfloat16 c1 = __float2bfloat16(v1 - __bfloat162float(a1));
                    *(unsigned*)(outH + pos) = pack_bf2(a0, a1);
                    *(unsigned*)(outL + pos) = pack_bf2(c0, c1);
                } else {
                    *(float2*)(outF + pos) = make_float2(v0, v1);
                }
            }
        }
}

// ---------------- launch -----------------------------------------------------
extern "C" void kernel_launch(void* const* d_in, const int* in_sizes, int n_in,
                              void* d_out, int out_size)
{
    const float* pos = (const float*)d_in[0];
    const int*   pts = (const int*)d_in[1];
    const float* W1  = (const float*)d_in[2];
    const float* b1  = (const float*)d_in[3];
    const float* W2  = (const float*)d_in[4];
    const float* b2  = (const float*)d_in[5];
    const float* Wk1 = (const float*)d_in[6];
    const float* bk1 = (const float*)d_in[7];
    const float* Wk2 = (const float*)d_in[8];
    const float* bk2 = (const float*)d_in[9];
    const float* Cw1 = (const float*)d_in[10];
    const float* Cb1 = (const float*)d_in[11];
    const float* Cw2 = (const float*)d_in[12];
    const float* Cb2 = (const float*)d_in[13];
    float* out = (float*)d_out;

    void *pSums, *pCnt, *pXh, *pXl, *pYh, *pYl, *pW1h, *pW1l, *pW2h, *pW2l;
    cudaGetSymbolAddress(&pSums, g_sums);
    cudaGetSymbolAddress(&pCnt,  g_cnt);
    cudaGetSymbolAddress(&pXh,   g_xh);
    cudaGetSymbolAddress(&pXl,   g_xl);
    cudaGetSymbolAddress(&pYh,   g_yh);
    cudaGetSymbolAddress(&pYl,   g_yl);
    cudaGetSymbolAddress(&pW1h,  g_w1h);
    cudaGetSymbolAddress(&pW1l,  g_w1l);
    cudaGetSymbolAddress(&pW2h,  g_w2h);
    cudaGetSymbolAddress(&pW2l,  g_w2l);

    cudaFuncSetAttribute(conv_mma<true>,  cudaFuncAttributeMaxDynamicSharedMemorySize, CONV_SMEM);
    cudaFuncSetAttribute(conv_mma<false>, cudaFuncAttributeMaxDynamicSharedMemorySize, CONV_SMEM);

    cudaMemsetAsync(pSums, 0, sizeof(float) * (size_t)S * L);
    cudaMemsetAsync(pCnt,  0, sizeof(float) * (size_t)S);

    repack_split<<<432, 256>>>(Cw1, (__nv_bfloat16*)pW1h, (__nv_bfloat16*)pW1l);
    repack_split<<<432, 256>>>(Cw2, (__nv_bfloat16*)pW2h, (__nv_bfloat16*)pW2l);

    mlp_scatter<<<2368, 256>>>(pos, pts, W1, b1, W2, b2, Wk1, bk1, Wk2, bk2);
    normalize_split<<<16384, 256>>>();

    conv_mma<true><<<2048, 256, CONV_SMEM>>>(
        (const __nv_bfloat16*)pXh, (const __nv_bfloat16*)pXl,
        (const __nv_bfloat16*)pW1h, (const __nv_bfloat16*)pW1l, Cb1,
        nullptr, (__nv_bfloat16*)pYh, (__nv_bfloat16*)pYl);
    conv_mma<false><<<2048, 256, CONV_SMEM>>>(
        (const __nv_bfloat16*)pYh, (const __nv_bfloat16*)pYl,
        (const __nv_bfloat16*)pW2h, (const __nv_bfloat16*)pW2l, Cb2,
        out, nullptr, nullptr);
}

// round 6
// speedup vs baseline: 3.3559x; 1.1820x over previous
#include <cuda_runtime.h>
#include <cuda_bf16.h>

#define G 64
#define S (G*G*G)
#define L 64
#define NPTS 150000
#define PADW 72                      // padded row stride (144B): ldmatrix conflict-free

// ---------------- scratch (device globals; no allocation allowed) ----------
__device__ float g_sums[S*L];                                  // 67 MB
__device__ float g_cnt[S];                                     // 1 MB
__device__ __align__(16) __nv_bfloat16 g_yh[S*L], g_yl[S*L];   // conv1 out hi/lo
__device__ __align__(16) __nv_bfloat16 g_w1h[27*L*L], g_w1l[27*L*L];  // [t][o][i]
__device__ __align__(16) __nv_bfloat16 g_w2h[27*L*L], g_w2l[27*L*L];
__device__ __align__(16) __nv_bfloat16 g_w2th[L*L], g_w2tl[L*L];      // W2^T [o][l]

__device__ __forceinline__ unsigned pack_bf2(__nv_bfloat16 a, __nv_bfloat16 b) {
    return ((unsigned)__bfloat16_as_ushort(b) << 16) | (unsigned)__bfloat16_as_ushort(a);
}
__device__ __forceinline__ void split_pack2(float a, float b, unsigned& h, unsigned& l) {
    __nv_bfloat16 ah = __float2bfloat16(a), bh = __float2bfloat16(b);
    __nv_bfloat16 al = __float2bfloat16(a - __bfloat162float(ah));
    __nv_bfloat16 bl = __float2bfloat16(b - __bfloat162float(bh));
    h = pack_bf2(ah, bh); l = pack_bf2(al, bl);
}
__device__ __forceinline__ void ldsm4(unsigned addr, unsigned& r0, unsigned& r1,
                                      unsigned& r2, unsigned& r3) {
    asm volatile("ldmatrix.sync.aligned.m8n8.x4.shared.b16 {%0,%1,%2,%3}, [%4];"
        : "=r"(r0), "=r"(r1), "=r"(r2), "=r"(r3) : "r"(addr));
}
__device__ __forceinline__ void mma16816(float* c, const unsigned* a,
                                         unsigned b0, unsigned b1) {
    asm volatile("mma.sync.aligned.m16n8k16.row.col.f32.bf16.bf16.f32 "
        "{%0,%1,%2,%3}, {%4,%5,%6,%7}, {%8,%9}, {%0,%1,%2,%3};"
        : "+f"(c[0]), "+f"(c[1]), "+f"(c[2]), "+f"(c[3])
        : "r"(a[0]), "r"(a[1]), "r"(a[2]), "r"(a[3]), "r"(b0), "r"(b1));
}

// ---------------- combined repack: conv weights [t][o][i] + W2^T, hi/lo -----
__global__ void repack_all(const float* __restrict__ Cw1,
                           const float* __restrict__ Cw2,
                           const float* __restrict__ W2) {
    int b = blockIdx.x;
    if (b < 864) {
        int idx = (b % 432) * 256 + threadIdx.x;
        if (idx >= 27*64*64) return;
        int t = idx >> 12, r = idx & 4095;
        int o = r >> 6, i = r & 63;
        const float* src = (b < 432) ? Cw1 : Cw2;
        float v = src[(o*64 + i)*27 + t];
        __nv_bfloat16 h = __float2bfloat16(v);
        __nv_bfloat16 l = __float2bfloat16(v - __bfloat162float(h));
        if (b < 432) { g_w1h[idx] = h; g_w1l[idx] = l; }
        else         { g_w2h[idx] = h; g_w2l[idx] = l; }
    } else {
        int idx = (b - 864) * 256 + threadIdx.x;   // o = idx>>6, l = idx&63
        int o = idx >> 6, l = idx & 63;
        float v = W2[l*64 + o];
        __nv_bfloat16 h = __float2bfloat16(v);
        g_w2th[idx] = h;
        g_w2tl[idx] = __float2bfloat16(v - __bfloat162float(h));
    }
}

// ---------------- tensor-core point MLP + atomic scatter --------------------
#define MA_BYTES (2*128*PADW*2)          // 36864 (reused for feat fp32 [128][66])
#define MW_BYTES (2*64*PADW*2)           // 18432
#define MC_OFF   (MA_BYTES + MW_BYTES)   // 55296
#define MLP_SMEM (MC_OFF + 3328)

__global__ void __launch_bounds__(256) mlp_tc(
    const float* __restrict__ pos, const int* __restrict__ pts,
    const float* __restrict__ W1, const float* __restrict__ b1,
    const float* __restrict__ b2,
    const float* __restrict__ Wk1, const float* __restrict__ bk1,
    const float* __restrict__ Wk2, const float* __restrict__ bk2)
{
    extern __shared__ __align__(16) char sm[];
    __nv_bfloat16* smA = (__nv_bfloat16*)sm;               // [hl][128][PADW]
    __nv_bfloat16* smB = (__nv_bfloat16*)(sm + MA_BYTES);  // [hl][64 o][PADW]
    float* smC   = (float*)(sm + MC_OFF);
    float* pos_s = smC;            // 384
    float* W1s   = smC + 384;      // 192
    float* b1s   = smC + 576;      // 64
    float* b2s   = smC + 640;      // 64
    float* Wk1s  = smC + 704;      // 64
    float* bk1s  = smC + 768;      // 8
    float* Wk2s  = smC + 776;      // 8
    float* bk2s  = smC + 784;      // 1
    int*   cell_s = (int*)(smC + 788); // 16
    float* feat_s = (float*)sm;    // [128][66] fp32, reuses A region after MMA

    const unsigned Abase = (unsigned)__cvta_generic_to_shared(smA);
    const unsigned Bbase = (unsigned)__cvta_generic_to_shared(smB);
    const int tid = threadIdx.x, wid = tid >> 5, lane = tid & 31;
    const int p0 = blockIdx.x * 16;

    {
        int i = tid;        if (i < 384) pos_s[i] = pos[(size_t)p0*24 + i];
        i = tid + 256;      if (i < 384) pos_s[i] = pos[(size_t)p0*24 + i];
        if (tid < 192) W1s[tid] = W1[tid];
        if (tid < 64)  { b1s[tid] = b1[tid]; b2s[tid] = b2[tid]; Wk1s[tid] = Wk1[tid]; }
        if (tid < 8)   { bk1s[tid] = bk1[tid]; Wk2s[tid] = Wk2[tid]; }
        if (tid == 0)  bk2s[0] = bk2[0];
        if (tid < 16) {
            int p = p0 + tid;
            cell_s[tid] = (pts[p*3]*G + pts[p*3+1])*G + pts[p*3+2];
        }
        for (int idx = tid; idx < 1024; idx += 256) {   // W2T tiles
            int row = idx >> 3, ch = idx & 7;
            int hl = row >> 6, o = row & 63;
            const __nv_bfloat16* s = (hl ? g_w2tl : g_w2th) + o*64 + ch*8;
            *(float4*)(smB + (hl*64 + o)*PADW + ch*8) = *(const float4*)s;
        }
    }
    __syncthreads();

    // h = lrelu(pos@W1 + b1) -> smA bf16 hi/lo
    {
        int r = tid >> 1, l0 = (tid & 1) * 32;
        int p = r >> 3, k = r & 7;
        float px = pos_s[p*24 + k*3 + 0];
        float py = pos_s[p*24 + k*3 + 1];
        float pz = pos_s[p*24 + k*3 + 2];
        unsigned* dH = (unsigned*)(smA + r*PADW + l0);
        unsigned* dL = (unsigned*)(smA + (128 + r)*PADW + l0);
        #pragma unroll
        for (int j = 0; j < 16; ++j) {
            int l = l0 + j*2;
            float v0 = px*W1s[l]   + py*W1s[64+l]   + pz*W1s[128+l]   + b1s[l];
            float v1 = px*W1s[l+1] + py*W1s[64+l+1] + pz*W1s[128+l+1] + b1s[l+1];
            v0 = v0 >= 0.f ? v0 : 0.01f*v0;
            v1 = v1 >= 0.f ? v1 : 0.01f*v1;
            unsigned hp, lp;
            split_pack2(v0, v1, hp, lp);
            dH[j] = hp; dL[j] = lp;
        }
    }
    __syncthreads();

    // feat = h @ W2 (3-term bf16 mma), warp tile 32x32
    const int warp_m = wid & 3, warp_n = wid >> 2;
    const int t8 = lane >> 3, lr = lane & 7;
    unsigned aOff[2][2], bOff[2][2];
    #pragma unroll
    for (int hl = 0; hl < 2; ++hl) {
        #pragma unroll
        for (int mb = 0; mb < 2; ++mb) {
            int r = warp_m*32 + mb*16 + (t8 & 1)*8 + lr;
            aOff[hl][mb] = (unsigned)(((hl*128 + r)*PADW + (t8 >> 1)*8) * 2);
        }
        #pragma unroll
        for (int pr = 0; pr < 2; ++pr) {
            int n = warp_n*32 + pr*16 + (t8 >> 1)*8 + lr;
            bOff[hl][pr] = (unsigned)(((hl*64 + n)*PADW + (t8 & 1)*8) * 2);
        }
    }
    float acc[2][4][4];
    #pragma unroll
    for (int mb = 0; mb < 2; ++mb)
        #pragma unroll
        for (int nb = 0; nb < 4; ++nb)
            #pragma unroll
            for (int q = 0; q < 4; ++q) acc[mb][nb][q] = 0.f;

    #pragma unroll
    for (int k0 = 0; k0 < 64; k0 += 16) {
        unsigned ah[2][4], al[2][4], bh[2][4], bl[2][4];
        #pragma unroll
        for (int mb = 0; mb < 2; ++mb) {
            ldsm4(Abase + aOff[0][mb] + k0*2, ah[mb][0], ah[mb][1], ah[mb][2], ah[mb][3]);
            ldsm4(Abase + aOff[1][mb] + k0*2, al[mb][0], al[mb][1], al[mb][2], al[mb][3]);
        }
        #pragma unroll
        for (int pr = 0; pr < 2; ++pr) {
            ldsm4(Bbase + bOff[0][pr] + k0*2, bh[pr][0], bh[pr][1], bh[pr][2], bh[pr][3]);
            ldsm4(Bbase + bOff[1][pr] + k0*2, bl[pr][0], bl[pr][1], bl[pr][2], bl[pr][3]);
        }
        #pragma unroll
        for (int mb = 0; mb < 2; ++mb)
            #pragma unroll
            for (int nb = 0; nb < 4; ++nb) {
                int pr = nb >> 1, sel = (nb & 1) << 1;
                mma16816(acc[mb][nb], ah[mb], bh[pr][sel], bh[pr][sel+1]);
                mma16816(acc[mb][nb], ah[mb], bl[pr][sel], bl[pr][sel+1]);
                mma16816(acc[mb][nb], al[mb], bh[pr][sel], bh[pr][sel+1]);
            }
    }
    __syncthreads();

    // spill feat (+b2) fp32 to smem
    {
        const int gid = lane >> 2, qid = lane & 3;
        #pragma unroll
        for (int mb = 0; mb < 2; ++mb)
            #pragma unroll
            for (int nb = 0; nb < 4; ++nb) {
                int n = warp_n*32 + nb*8 + qid*2;
                float2 bb = *(const float2*)&b2s[n];
                #pragma unroll
                for (int half = 0; half < 2; ++half) {
                    int m = warp_m*32 + mb*16 + gid + half*8;
                    *(float2*)&feat_s[m*66 + n] =
                        make_float2(acc[mb][nb][half*2+0] + bb.x,
                                    acc[mb][nb][half*2+1] + bb.y);
                }
            }
    }
    __syncthreads();

    // Wk1/Wk2 contraction + atomic scatter
    #pragma unroll
    for (int rep = 0; rep < 4; ++rep) {
        int idx = rep*256 + tid;
        int p = idx >> 6, l = idx & 63;
        float f[8];
        #pragma unroll
        for (int k = 0; k < 8; ++k) f[k] = feat_s[(p*8 + k)*66 + l];
        float f2 = bk2s[0];
        #pragma unroll
        for (int o = 0; o < 8; ++o) {
            float s = bk1s[o];
            #pragma unroll
            for (int k = 0; k < 8; ++k) s += Wk1s[o*8 + k] * f[k];
            s = s >= 0.f ? s : 0.01f*s;
            f2 += Wk2s[o] * s;
        }
        int cell = cell_s[p];
        atomicAdd(&g_sums[(size_t)cell*64 + l], f2);
        if (l == 0) atomicAdd(&g_cnt[cell], 1.0f);
    }
}

// ---------------- mma.sync conv3d (optionally fused normalize+split input) --
#define A_ELEMS (2*2*66*PADW)
#define W_ELEMS (2*64*PADW)
#define CONV_SMEM ((A_ELEMS + W_ELEMS) * 2)

template<bool SPLIT_OUT, bool READ_F32>
__global__ void __launch_bounds__(256) conv_mma(
    const __nv_bfloat16* __restrict__ xh, const __nv_bfloat16* __restrict__ xl,
    const float* __restrict__ xf, const float* __restrict__ xcnt,
    const __nv_bfloat16* __restrict__ wth, const __nv_bfloat16* __restrict__ wtl,
    const float* __restrict__ bias,
    float* __restrict__ outF,
    __nv_bfloat16* __restrict__ outH, __nv_bfloat16* __restrict__ outL)
{
    extern __shared__ __align__(16) char sm_raw[];
    __nv_bfloat16* smA = (__nv_bfloat16*)sm_raw;                 // [hl][hrow][66][PADW]
    __nv_bfloat16* smW = (__nv_bfloat16*)(sm_raw + A_ELEMS*2);   // [hl][o][PADW]
    const unsigned Abase = (unsigned)__cvta_generic_to_shared(smA);
    const unsigned Wbase = (unsigned)__cvta_generic_to_shared(smW);

    const int tid = threadIdx.x;
    const int wid = tid >> 5, lane = tid & 31;
    const int d0 = blockIdx.x >> 5;
    const int h0 = (blockIdx.x & 31) << 1;
    const int warp_m = wid & 3, warp_n = wid >> 2;

    const int t8 = lane >> 3, lr = lane & 7;
    unsigned aOff[2][2], bOff[2][2];
    #pragma unroll
    for (int hl = 0; hl < 2; ++hl) {
        #pragma unroll
        for (int mb = 0; mb < 2; ++mb) {
            int r = warp_m*32 + mb*16 + (t8 & 1)*8 + lr;
            int hrow = r >> 6, w = r & 63;
            aOff[hl][mb] = (unsigned)((((hl*2 + hrow)*66 + w)*PADW + (t8 >> 1)*8) * 2);
        }
        #pragma unroll
        for (int pr = 0; pr < 2; ++pr) {
            int n = warp_n*32 + pr*16 + (t8 >> 1)*8 + lr;
            bOff[hl][pr] = (unsigned)(((hl*64 + n)*PADW + (t8 & 1)*8) * 2);
        }
    }

    float acc[2][4][4];
    #pragma unroll
    for (int mb = 0; mb < 2; ++mb)
        #pragma unroll
        for (int nb = 0; nb < 4; ++nb)
            #pragma unroll
            for (int q = 0; q < 4; ++q) acc[mb][nb][q] = 0.f;

    const int gA = tid >> 6, hlA = gA >> 1, hrA4 = gA & 1, wA = tid & 63;

    for (int dzy = 0; dzy < 9; ++dzy) {
        const int dz = dzy / 3, dy = dzy % 3;
        const int dd = d0 + dz - 1;
        if ((unsigned)dd >= (unsigned)G) continue;

        __syncthreads();
        if (READ_F32) {
            const int hrA = tid >> 7;
            const int wA2 = (tid >> 1) & 63;
            const int cH = tid & 1;
            const int hin = h0 + dy - 1 + hrA;
            uint2* dH = (uint2*)(smA + ((0 + hrA)*66 + wA2 + 1)*PADW + cH*32);
            uint2* dL = (uint2*)(smA + ((2 + hrA)*66 + wA2 + 1)*PADW + cH*32);
            if ((unsigned)hin < (unsigned)G) {
                size_t cell = (size_t)(dd*G + hin)*G + wA2;
                float c = xcnt[cell];
                float inv = c > 0.f ? 1.f/c : 0.f;
                const float4* s4 = (const float4*)(xf + cell*64 + cH*32);
                #pragma unroll
                for (int j = 0; j < 8; ++j) {
                    float4 v = s4[j];
                    unsigned hp0, lp0, hp1, lp1;
                    split_pack2(v.x*inv, v.y*inv, hp0, lp0);
                    split_pack2(v.z*inv, v.w*inv, hp1, lp1);
                    dH[j] = make_uint2(hp0, hp1);
                    dL[j] = make_uint2(lp0, lp1);
                }
            } else {
                uint2 z = make_uint2(0u, 0u);
                #pragma unroll
                for (int j = 0; j < 8; ++j) { dH[j] = z; dL[j] = z; }
            }
            if (wA2 == 0) {
                uint2 z = make_uint2(0u, 0u);
                uint2* zh = (uint2*)(smA + ((0 + hrA)*66)*PADW + cH*32);
                uint2* zl = (uint2*)(smA + ((2 + hrA)*66)*PADW + cH*32);
                #pragma unroll
                for (int j = 0; j < 8; ++j) { zh[j] = z; zl[j] = z; }
            }
            if (wA2 == 63) {
                uint2 z = make_uint2(0u, 0u);
                uint2* zh = (uint2*)(smA + ((0 + hrA)*66 + 65)*PADW + cH*32);
                uint2* zl = (uint2*)(smA + ((2 + hrA)*66 + 65)*PADW + cH*32);
                #pragma unroll
                for (int j = 0; j < 8; ++j) { zh[j] = z; zl[j] = z; }
            }
        } else {
            const int hin = h0 + dy - 1 + hrA4;
            __nv_bfloat16* dstA = smA + ((hlA*2 + hrA4)*66 + (wA + 1))*PADW;
            const __nv_bfloat16* srcA_base = hlA ? xl : xh;
            float4* d4 = (float4*)dstA;
            if ((unsigned)hin < (unsigned)G) {
                const float4* s4 = (const float4*)(srcA_base +
                    (((size_t)(dd*G + hin))*G + wA) * 64);
                #pragma unroll
                for (int j = 0; j < 8; ++j) d4[j] = s4[j];
            } else {
                float4 z = make_float4(0.f, 0.f, 0.f, 0.f);
                #pragma unroll
                for (int j = 0; j < 8; ++j) d4[j] = z;
            }
            if (wA == 0) {
                float4 z = make_float4(0.f, 0.f, 0.f, 0.f);
                float4* h4 = (float4*)(smA + ((hlA*2 + hrA4)*66)*PADW);
                #pragma unroll
                for (int j = 0; j < 8; ++j) h4[j] = z;
            }
            if (wA == 63) {
                float4 z = make_float4(0.f, 0.f, 0.f, 0.f);
                float4* h4 = (float4*)(smA + ((hlA*2 + hrA4)*66 + 65)*PADW);
                #pragma unroll
                for (int j = 0; j < 8; ++j) h4[j] = z;
            }
        }

        for (int dx = 0; dx < 3; ++dx) {
            const int tap = dzy*3 + dx;
            __syncthreads();
            for (int idx = tid; idx < 1024; idx += 256) {
                int row = idx >> 3, cch = idx & 7;
                int hl = row >> 6, o = row & 63;
                const __nv_bfloat16* s = (hl ? wtl : wth) + ((size_t)tap*4096 + o*64 + cch*8);
                *(float4*)(smW + (hl*64 + o)*PADW + cch*8) = *(const float4*)s;
            }
            __syncthreads();

            const unsigned Adx = Abase + (unsigned)(dx * PADW * 2);
            #pragma unroll
            for (int k0 = 0; k0 < 64; k0 += 16) {
                unsigned ah[2][4], al[2][4], bh[2][4], bl[2][4];
                #pragma unroll
                for (int mb = 0; mb < 2; ++mb) {
                    ldsm4(Adx + aOff[0][mb] + k0*2, ah[mb][0], ah[mb][1], ah[mb][2], ah[mb][3]);
                    ldsm4(Adx + aOff[1][mb] + k0*2, al[mb][0], al[mb][1], al[mb][2], al[mb][3]);
                }
                #pragma unroll
                for (int pr = 0; pr < 2; ++pr) {
                    ldsm4(Wbase + bOff[0][pr] + k0*2, bh[pr][0], bh[pr][1], bh[pr][2], bh[pr][3]);
                    ldsm4(Wbase + bOff[1][pr] + k0*2, bl[pr][0], bl[pr][1], bl[pr][2], bl[pr][3]);
                }
                #pragma unroll
                for (int mb = 0; mb < 2; ++mb)
                    #pragma unroll
                    for (int nb = 0; nb < 4; ++nb) {
                        int pr = nb >> 1, sel = (nb & 1) << 1;
                        mma16816(acc[mb][nb], ah[mb], bh[pr][sel], bh[pr][sel+1]);
                        mma16816(acc[mb][nb], ah[mb], bl[pr][sel], bl[pr][sel+1]);
                        mma16816(acc[mb][nb], al[mb], bh[pr][sel], bh[pr][sel+1]);
                    }
            }
        }
    }

    const int gid = lane >> 2, qid = lane & 3;
    #pragma unroll
    for (int mb = 0; mb < 2; ++mb)
        #pragma unroll
        for (int nb = 0; nb < 4; ++nb) {
            int n = warp_n*32 + nb*8 + qid*2;
            float2 bb = *(const float2*)&bias[n];
            #pragma unroll
            for (int half = 0; half < 2; ++half) {
                int m = warp_m*32 + mb*16 + gid + half*8;
                int hrow = m >> 6, w = m & 63;
                size_t pos = ((size_t)((d0*G + h0 + hrow)*G + w))*64 + n;
                float v0 = fmaxf(acc[mb][nb][half*2+0] + bb.x, 0.f);
                float v1 = fmaxf(acc[mb][nb][half*2+1] + bb.y, 0.f);
                if (SPLIT_OUT) {
                    unsigned hp, lp;
                    split_pack2(v0, v1, hp, lp);
                    *(unsigned*)(outH + pos) = hp;
                    *(unsigned*)(outL + pos) = lp;
                } else {
                    *(float2*)(outF + pos) = make_float2(v0, v1);
                }
            }
        }
}

// ---------------- launch -----------------------------------------------------
extern "C" void kernel_launch(void* const* d_in, const int* in_sizes, int n_in,
                              void* d_out, int out_size)
{
    const float* pos = (const float*)d_in[0];
    const int*   pts = (const int*)d_in[1];
    const float* W1  = (const float*)d_in[2];
    const float* b1  = (const float*)d_in[3];
    const float* W2  = (const float*)d_in[4];
    const float* b2  = (const float*)d_in[5];
    const float* Wk1 = (const float*)d_in[6];
    const float* bk1 = (const float*)d_in[7];
    const float* Wk2 = (const float*)d_in[8];
    const float* bk2 = (const float*)d_in[9];
    const float* Cw1 = (const float*)d_in[10];
    const float* Cb1 = (const float*)d_in[11];
    const float* Cw2 = (const float*)d_in[12];
    const float* Cb2 = (const float*)d_in[13];
    float* out = (float*)d_out;

    void *pSums, *pCnt, *pYh, *pYl, *pW1h, *pW1l, *pW2h, *pW2l;
    cudaGetSymbolAddress(&pSums, g_sums);
    cudaGetSymbolAddress(&pCnt,  g_cnt);
    cudaGetSymbolAddress(&pYh,   g_yh);
    cudaGetSymbolAddress(&pYl,   g_yl);
    cudaGetSymbolAddress(&pW1h,  g_w1h);
    cudaGetSymbolAddress(&pW1l,  g_w1l);
    cudaGetSymbolAddress(&pW2h,  g_w2h);
    cudaGetSymbolAddress(&pW2l,  g_w2l);

    cudaFuncSetAttribute(mlp_tc, cudaFuncAttributeMaxDynamicSharedMemorySize, MLP_SMEM);
    cudaFuncSetAttribute(conv_mma<true,true>,   cudaFuncAttributeMaxDynamicSharedMemorySize, CONV_SMEM);
    cudaFuncSetAttribute(conv_mma<false,false>, cudaFuncAttributeMaxDynamicSharedMemorySize, CONV_SMEM);

    cudaMemsetAsync(pSums, 0, sizeof(float) * (size_t)S * L);
    cudaMemsetAsync(pCnt,  0, sizeof(float) * (size_t)S);

    repack_all<<<880, 256>>>(Cw1, Cw2, W2);
    mlp_tc<<<NPTS/16, 256, MLP_SMEM>>>(pos, pts, W1, b1, b2, Wk1, bk1, Wk2, bk2);
    conv_mma<true,true><<<2048, 256, CONV_SMEM>>>(
        nullptr, nullptr, (const float*)pSums, (const float*)pCnt,
        (const __nv_bfloat16*)pW1h, (const __nv_bfloat16*)pW1l, Cb1,
        nullptr, (__nv_bfloat16*)pYh, (__nv_bfloat16*)pYl);
    conv_mma<false,false><<<2048, 256, CONV_SMEM>>>(
        (const __nv_bfloat16*)pYh, (const __nv_bfloat16*)pYl, nullptr, nullptr,
        (const __nv_bfloat16*)pW2h, (const __nv_bfloat16*)pW2l, Cb2,
        out, nullptr, nullptr);
}

// round 7
// speedup vs baseline: 3.6028x; 1.0736x over previous
#include <cuda_runtime.h>
#include <cuda_bf16.h>

#define G 64
#define S (G*G*G)
#define L 64
#define NPTS 150000
#define PADW 72                      // padded row stride (144B): ldmatrix conflict-free

// ---------------- scratch (device globals; no allocation allowed) ----------
__device__ float g_sums[S*L];                                  // 67 MB
__device__ float g_cnt[S];                                     // 1 MB
__device__ __align__(16) __nv_bfloat16 g_yh[S*L], g_yl[S*L];   // conv1 out hi/lo
__device__ __align__(16) __nv_bfloat16 g_w1h[27*L*L], g_w1l[27*L*L];  // [t][o][i]
__device__ __align__(16) __nv_bfloat16 g_w2h[27*L*L], g_w2l[27*L*L];
__device__ __align__(16) __nv_bfloat16 g_w2th[L*L], g_w2tl[L*L];      // W2^T [o][l]

__device__ __forceinline__ unsigned pack_bf2(__nv_bfloat16 a, __nv_bfloat16 b) {
    return ((unsigned)__bfloat16_as_ushort(b) << 16) | (unsigned)__bfloat16_as_ushort(a);
}
__device__ __forceinline__ void split_pack2(float a, float b, unsigned& h, unsigned& l) {
    __nv_bfloat16 ah = __float2bfloat16(a), bh = __float2bfloat16(b);
    __nv_bfloat16 al = __float2bfloat16(a - __bfloat162float(ah));
    __nv_bfloat16 bl = __float2bfloat16(b - __bfloat162float(bh));
    h = pack_bf2(ah, bh); l = pack_bf2(al, bl);
}
__device__ __forceinline__ void ldsm4(unsigned addr, unsigned& r0, unsigned& r1,
                                      unsigned& r2, unsigned& r3) {
    asm volatile("ldmatrix.sync.aligned.m8n8.x4.shared.b16 {%0,%1,%2,%3}, [%4];"
        : "=r"(r0), "=r"(r1), "=r"(r2), "=r"(r3) : "r"(addr));
}
__device__ __forceinline__ void mma16816(float* c, const unsigned* a,
                                         unsigned b0, unsigned b1) {
    asm volatile("mma.sync.aligned.m16n8k16.row.col.f32.bf16.bf16.f32 "
        "{%0,%1,%2,%3}, {%4,%5,%6,%7}, {%8,%9}, {%0,%1,%2,%3};"
        : "+f"(c[0]), "+f"(c[1]), "+f"(c[2]), "+f"(c[3])
        : "r"(a[0]), "r"(a[1]), "r"(a[2]), "r"(a[3]), "r"(b0), "r"(b1));
}

// ---------------- combined repack: conv weights [t][o][i] + W2^T, hi/lo -----
__global__ void repack_all(const float* __restrict__ Cw1,
                           const float* __restrict__ Cw2,
                           const float* __restrict__ W2) {
    int b = blockIdx.x;
    if (b < 864) {
        int idx = (b % 432) * 256 + threadIdx.x;
        if (idx >= 27*64*64) return;
        int t = idx >> 12, r = idx & 4095;
        int o = r >> 6, i = r & 63;
        const float* src = (b < 432) ? Cw1 : Cw2;
        float v = src[(o*64 + i)*27 + t];
        __nv_bfloat16 h = __float2bfloat16(v);
        __nv_bfloat16 l = __float2bfloat16(v - __bfloat162float(h));
        if (b < 432) { g_w1h[idx] = h; g_w1l[idx] = l; }
        else         { g_w2h[idx] = h; g_w2l[idx] = l; }
    } else {
        int idx = (b - 864) * 256 + threadIdx.x;   // o = idx>>6, l = idx&63
        int o = idx >> 6, l = idx & 63;
        float v = W2[l*64 + o];
        __nv_bfloat16 h = __float2bfloat16(v);
        g_w2th[idx] = h;
        g_w2tl[idx] = __float2bfloat16(v - __bfloat162float(h));
    }
}

// ---------------- tensor-core point MLP + atomic scatter (R6, proven) -------
#define MA_BYTES (2*128*PADW*2)          // 36864 (reused for feat fp32 [128][66])
#define MW_BYTES (2*64*PADW*2)           // 18432
#define MC_OFF   (MA_BYTES + MW_BYTES)   // 55296
#define MLP_SMEM (MC_OFF + 3328)

__global__ void __launch_bounds__(256) mlp_tc(
    const float* __restrict__ pos, const int* __restrict__ pts,
    const float* __restrict__ W1, const float* __restrict__ b1,
    const float* __restrict__ b2,
    const float* __restrict__ Wk1, const float* __restrict__ bk1,
    const float* __restrict__ Wk2, const float* __restrict__ bk2)
{
    extern __shared__ __align__(16) char sm[];
    __nv_bfloat16* smA = (__nv_bfloat16*)sm;               // [hl][128][PADW]
    __nv_bfloat16* smB = (__nv_bfloat16*)(sm + MA_BYTES);  // [hl][64 o][PADW]
    float* smC   = (float*)(sm + MC_OFF);
    float* pos_s = smC;            // 384
    float* W1s   = smC + 384;      // 192
    float* b1s   = smC + 576;      // 64
    float* b2s   = smC + 640;      // 64
    float* Wk1s  = smC + 704;      // 64
    float* bk1s  = smC + 768;      // 8
    float* Wk2s  = smC + 776;      // 8
    float* bk2s  = smC + 784;      // 1
    int*   cell_s = (int*)(smC + 788); // 16
    float* feat_s = (float*)sm;    // [128][66] fp32, reuses A region after MMA

    const unsigned Abase = (unsigned)__cvta_generic_to_shared(smA);
    const unsigned Bbase = (unsigned)__cvta_generic_to_shared(smB);
    const int tid = threadIdx.x, wid = tid >> 5, lane = tid & 31;
    const int p0 = blockIdx.x * 16;

    {
        int i = tid;        if (i < 384) pos_s[i] = pos[(size_t)p0*24 + i];
        i = tid + 256;      if (i < 384) pos_s[i] = pos[(size_t)p0*24 + i];
        if (tid < 192) W1s[tid] = W1[tid];
        if (tid < 64)  { b1s[tid] = b1[tid]; b2s[tid] = b2[tid]; Wk1s[tid] = Wk1[tid]; }
        if (tid < 8)   { bk1s[tid] = bk1[tid]; Wk2s[tid] = Wk2[tid]; }
        if (tid == 0)  bk2s[0] = bk2[0];
        if (tid < 16) {
            int p = p0 + tid;
            cell_s[tid] = (pts[p*3]*G + pts[p*3+1])*G + pts[p*3+2];
        }
        for (int idx = tid; idx < 1024; idx += 256) {
            int row = idx >> 3, ch = idx & 7;
            int hl = row >> 6, o = row & 63;
            const __nv_bfloat16* s = (hl ? g_w2tl : g_w2th) + o*64 + ch*8;
            *(float4*)(smB + (hl*64 + o)*PADW + ch*8) = *(const float4*)s;
        }
    }
    __syncthreads();

    {
        int r = tid >> 1, l0 = (tid & 1) * 32;
        int p = r >> 3, k = r & 7;
        float px = pos_s[p*24 + k*3 + 0];
        float py = pos_s[p*24 + k*3 + 1];
        float pz = pos_s[p*24 + k*3 + 2];
        unsigned* dH = (unsigned*)(smA + r*PADW + l0);
        unsigned* dL = (unsigned*)(smA + (128 + r)*PADW + l0);
        #pragma unroll
        for (int j = 0; j < 16; ++j) {
            int l = l0 + j*2;
            float v0 = px*W1s[l]   + py*W1s[64+l]   + pz*W1s[128+l]   + b1s[l];
            float v1 = px*W1s[l+1] + py*W1s[64+l+1] + pz*W1s[128+l+1] + b1s[l+1];
            v0 = v0 >= 0.f ? v0 : 0.01f*v0;
            v1 = v1 >= 0.f ? v1 : 0.01f*v1;
            unsigned hp, lp;
            split_pack2(v0, v1, hp, lp);
            dH[j] = hp; dL[j] = lp;
        }
    }
    __syncthreads();

    const int warp_m = wid & 3, warp_n = wid >> 2;
    const int t8 = lane >> 3, lr = lane & 7;
    unsigned aOff[2][2], bOff[2][2];
    #pragma unroll
    for (int hl = 0; hl < 2; ++hl) {
        #pragma unroll
        for (int mb = 0; mb < 2; ++mb) {
            int r = warp_m*32 + mb*16 + (t8 & 1)*8 + lr;
            aOff[hl][mb] = (unsigned)(((hl*128 + r)*PADW + (t8 >> 1)*8) * 2);
        }
        #pragma unroll
        for (int pr = 0; pr < 2; ++pr) {
            int n = warp_n*32 + pr*16 + (t8 >> 1)*8 + lr;
            bOff[hl][pr] = (unsigned)(((hl*64 + n)*PADW + (t8 & 1)*8) * 2);
        }
    }
    float acc[2][4][4];
    #pragma unroll
    for (int mb = 0; mb < 2; ++mb)
        #pragma unroll
        for (int nb = 0; nb < 4; ++nb)
            #pragma unroll
            for (int q = 0; q < 4; ++q) acc[mb][nb][q] = 0.f;

    #pragma unroll
    for (int k0 = 0; k0 < 64; k0 += 16) {
        unsigned ah[2][4], al[2][4], bh[2][4], bl[2][4];
        #pragma unroll
        for (int mb = 0; mb < 2; ++mb) {
            ldsm4(Abase + aOff[0][mb] + k0*2, ah[mb][0], ah[mb][1], ah[mb][2], ah[mb][3]);
            ldsm4(Abase + aOff[1][mb] + k0*2, al[mb][0], al[mb][1], al[mb][2], al[mb][3]);
        }
        #pragma unroll
        for (int pr = 0; pr < 2; ++pr) {
            ldsm4(Bbase + bOff[0][pr] + k0*2, bh[pr][0], bh[pr][1], bh[pr][2], bh[pr][3]);
            ldsm4(Bbase + bOff[1][pr] + k0*2, bl[pr][0], bl[pr][1], bl[pr][2], bl[pr][3]);
        }
        #pragma unroll
        for (int mb = 0; mb < 2; ++mb)
            #pragma unroll
            for (int nb = 0; nb < 4; ++nb) {
                int pr = nb >> 1, sel = (nb & 1) << 1;
                mma16816(acc[mb][nb], ah[mb], bh[pr][sel], bh[pr][sel+1]);
                mma16816(acc[mb][nb], ah[mb], bl[pr][sel], bl[pr][sel+1]);
                mma16816(acc[mb][nb], al[mb], bh[pr][sel], bh[pr][sel+1]);
            }
    }
    __syncthreads();

    {
        const int gid = lane >> 2, qid = lane & 3;
        #pragma unroll
        for (int mb = 0; mb < 2; ++mb)
            #pragma unroll
            for (int nb = 0; nb < 4; ++nb) {
                int n = warp_n*32 + nb*8 + qid*2;
                float2 bb = *(const float2*)&b2s[n];
                #pragma unroll
                for (int half = 0; half < 2; ++half) {
                    int m = warp_m*32 + mb*16 + gid + half*8;
                    *(float2*)&feat_s[m*66 + n] =
                        make_float2(acc[mb][nb][half*2+0] + bb.x,
                                    acc[mb][nb][half*2+1] + bb.y);
                }
            }
    }
    __syncthreads();

    #pragma unroll
    for (int rep = 0; rep < 4; ++rep) {
        int idx = rep*256 + tid;
        int p = idx >> 6, l = idx & 63;
        float f[8];
        #pragma unroll
        for (int k = 0; k < 8; ++k) f[k] = feat_s[(p*8 + k)*66 + l];
        float f2 = bk2s[0];
        #pragma unroll
        for (int o = 0; o < 8; ++o) {
            float s = bk1s[o];
            #pragma unroll
            for (int k = 0; k < 8; ++k) s += Wk1s[o*8 + k] * f[k];
            s = s >= 0.f ? s : 0.01f*s;
            f2 += Wk2s[o] * s;
        }
        int cell = cell_s[p];
        atomicAdd(&g_sums[(size_t)cell*64 + l], f2);
        if (l == 0) atomicAdd(&g_cnt[cell], 1.0f);
    }
}

// ---------------- mma.sync conv3d — 4 warps, warp tile 64x32 ----------------
// CTA: 2 h-rows x 64 w (M=128) x 64 out-ch (N=64); 128 threads.
// LDSM/MMA = 0.25 (vs 0.333 with 32x32 tiles) -> ~25% less L1 traffic.
#define A_ELEMS (2*2*66*PADW)
#define W_ELEMS (2*64*PADW)
#define CONV_SMEM ((A_ELEMS + W_ELEMS) * 2)

template<bool SPLIT_OUT, bool READ_F32>
__global__ void __launch_bounds__(128, 3) conv_mma(
    const __nv_bfloat16* __restrict__ xh, const __nv_bfloat16* __restrict__ xl,
    const float* __restrict__ xf, const float* __restrict__ xcnt,
    const __nv_bfloat16* __restrict__ wth, const __nv_bfloat16* __restrict__ wtl,
    const float* __restrict__ bias,
    float* __restrict__ outF,
    __nv_bfloat16* __restrict__ outH, __nv_bfloat16* __restrict__ outL)
{
    extern __shared__ __align__(16) char sm_raw[];
    __nv_bfloat16* smA = (__nv_bfloat16*)sm_raw;                 // [hl][hrow][66][PADW]
    __nv_bfloat16* smW = (__nv_bfloat16*)(sm_raw + A_ELEMS*2);   // [hl][o][PADW]
    const unsigned Abase = (unsigned)__cvta_generic_to_shared(smA);
    const unsigned Wbase = (unsigned)__cvta_generic_to_shared(smW);

    const int tid = threadIdx.x;
    const int wid = tid >> 5, lane = tid & 31;
    const int d0 = blockIdx.x >> 5;
    const int h0 = (blockIdx.x & 31) << 1;
    const int warp_m = wid & 1, warp_n = wid >> 1;   // m0 = warp_m*64, n0 = warp_n*32

    const int t8 = lane >> 3, lr = lane & 7;
    unsigned aOff[2][4], bOff[2][2];
    #pragma unroll
    for (int hl = 0; hl < 2; ++hl) {
        #pragma unroll
        for (int mb = 0; mb < 4; ++mb) {
            int r = warp_m*64 + mb*16 + (t8 & 1)*8 + lr;
            int hrow = r >> 6, w = r & 63;
            aOff[hl][mb] = (unsigned)((((hl*2 + hrow)*66 + w)*PADW + (t8 >> 1)*8) * 2);
        }
        #pragma unroll
        for (int pr = 0; pr < 2; ++pr) {
            int n = warp_n*32 + pr*16 + (t8 >> 1)*8 + lr;
            bOff[hl][pr] = (unsigned)(((hl*64 + n)*PADW + (t8 & 1)*8) * 2);
        }
    }

    float acc[4][4][4];
    #pragma unroll
    for (int mb = 0; mb < 4; ++mb)
        #pragma unroll
        for (int nb = 0; nb < 4; ++nb)
            #pragma unroll
            for (int q = 0; q < 4; ++q) acc[mb][nb][q] = 0.f;

    for (int dzy = 0; dzy < 9; ++dzy) {
        const int dz = dzy / 3, dy = dzy % 3;
        const int dd = d0 + dz - 1;
        if ((unsigned)dd >= (unsigned)G) continue;

        __syncthreads();
        if (READ_F32) {
            // tasks 0..255: hrow = t>>7, w = (t>>1)&63, cH = t&1
            for (int task = tid; task < 256; task += 128) {
                const int hrA = task >> 7;
                const int wA2 = (task >> 1) & 63;
                const int cH = task & 1;
                const int hin = h0 + dy - 1 + hrA;
                uint2* dH = (uint2*)(smA + ((0 + hrA)*66 + wA2 + 1)*PADW + cH*32);
                uint2* dL = (uint2*)(smA + ((2 + hrA)*66 + wA2 + 1)*PADW + cH*32);
                if ((unsigned)hin < (unsigned)G) {
                    size_t cell = (size_t)(dd*G + hin)*G + wA2;
                    float c = xcnt[cell];
                    float inv = c > 0.f ? 1.f/c : 0.f;
                    const float4* s4 = (const float4*)(xf + cell*64 + cH*32);
                    #pragma unroll
                    for (int j = 0; j < 8; ++j) {
                        float4 v = s4[j];
                        unsigned hp0, lp0, hp1, lp1;
                        split_pack2(v.x*inv, v.y*inv, hp0, lp0);
                        split_pack2(v.z*inv, v.w*inv, hp1, lp1);
                        dH[j] = make_uint2(hp0, hp1);
                        dL[j] = make_uint2(lp0, lp1);
                    }
                } else {
                    uint2 z = make_uint2(0u, 0u);
                    #pragma unroll
                    for (int j = 0; j < 8; ++j) { dH[j] = z; dL[j] = z; }
                }
                if (wA2 == 0) {
                    uint2 z = make_uint2(0u, 0u);
                    uint2* zh = (uint2*)(smA + ((0 + hrA)*66)*PADW + cH*32);
                    uint2* zl = (uint2*)(smA + ((2 + hrA)*66)*PADW + cH*32);
                    #pragma unroll
                    for (int j = 0; j < 8; ++j) { zh[j] = z; zl[j] = z; }
                }
                if (wA2 == 63) {
                    uint2 z = make_uint2(0u, 0u);
                    uint2* zh = (uint2*)(smA + ((0 + hrA)*66 + 65)*PADW + cH*32);
                    uint2* zl = (uint2*)(smA + ((2 + hrA)*66 + 65)*PADW + cH*32);
                    #pragma unroll
                    for (int j = 0; j < 8; ++j) { zh[j] = z; zl[j] = z; }
                }
            }
        } else {
            // tasks 0..255: g = t>>6 (hl = g>>1, hrow = g&1), w = t&63
            for (int task = tid; task < 256; task += 128) {
                const int gA = task >> 6, hlA = gA >> 1, hrA = gA & 1, wA = task & 63;
                const int hin = h0 + dy - 1 + hrA;
                __nv_bfloat16* dstA = smA + ((hlA*2 + hrA)*66 + (wA + 1))*PADW;
                const __nv_bfloat16* srcA_base = hlA ? xl : xh;
                float4* d4 = (float4*)dstA;
                if ((unsigned)hin < (unsigned)G) {
                    const float4* s4 = (const float4*)(srcA_base +
                        (((size_t)(dd*G + hin))*G + wA) * 64);
                    #pragma unroll
                    for (int j = 0; j < 8; ++j) d4[j] = s4[j];
                } else {
                    float4 z = make_float4(0.f, 0.f, 0.f, 0.f);
                    #pragma unroll
                    for (int j = 0; j < 8; ++j) d4[j] = z;
                }
                if (wA == 0) {
                    float4 z = make_float4(0.f, 0.f, 0.f, 0.f);
                    float4* h4 = (float4*)(smA + ((hlA*2 + hrA)*66)*PADW);
                    #pragma unroll
                    for (int j = 0; j < 8; ++j) h4[j] = z;
                }
                if (wA == 63) {
                    float4 z = make_float4(0.f, 0.f, 0.f, 0.f);
                    float4* h4 = (float4*)(smA + ((hlA*2 + hrA)*66 + 65)*PADW);
                    #pragma unroll
                    for (int j = 0; j < 8; ++j) h4[j] = z;
                }
            }
        }

        for (int dx = 0; dx < 3; ++dx) {
            const int tap = dzy*3 + dx;
            __syncthreads();
            for (int idx = tid; idx < 1024; idx += 128) {
                int row = idx >> 3, cch = idx & 7;
                int hl = row >> 6, o = row & 63;
                const __nv_bfloat16* s = (hl ? wtl : wth) + ((size_t)tap*4096 + o*64 + cch*8);
                *(float4*)(smW + (hl*64 + o)*PADW + cch*8) = *(const float4*)s;
            }
            __syncthreads();

            const unsigned Adx = Abase + (unsigned)(dx * PADW * 2);
            #pragma unroll
            for (int k0 = 0; k0 < 64; k0 += 16) {
                unsigned bh[2][4], bl[2][4];
                #pragma unroll
                for (int pr = 0; pr < 2; ++pr) {
                    ldsm4(Wbase + bOff[0][pr] + k0*2, bh[pr][0], bh[pr][1], bh[pr][2], bh[pr][3]);
                    ldsm4(Wbase + bOff[1][pr] + k0*2, bl[pr][0], bl[pr][1], bl[pr][2], bl[pr][3]);
                }
                #pragma unroll
                for (int mb = 0; mb < 4; ++mb) {
                    unsigned ah[4], al[4];
                    ldsm4(Adx + aOff[0][mb] + k0*2, ah[0], ah[1], ah[2], ah[3]);
                    ldsm4(Adx + aOff[1][mb] + k0*2, al[0], al[1], al[2], al[3]);
                    #pragma unroll
                    for (int nb = 0; nb < 4; ++nb) {
                        int pr = nb >> 1, sel = (nb & 1) << 1;
                        mma16816(acc[mb][nb], ah, bh[pr][sel], bh[pr][sel+1]);
                        mma16816(acc[mb][nb], ah, bl[pr][sel], bl[pr][sel+1]);
                        mma16816(acc[mb][nb], al, bh[pr][sel], bh[pr][sel+1]);
                    }
                }
            }
        }
    }

    const int gid = lane >> 2, qid = lane & 3;
    #pragma unroll
    for (int mb = 0; mb < 4; ++mb)
        #pragma unroll
        for (int nb = 0; nb < 4; ++nb) {
            int n = warp_n*32 + nb*8 + qid*2;
            float2 bb = *(const float2*)&bias[n];
            #pragma unroll
            for (int half = 0; half < 2; ++half) {
                int m = warp_m*64 + mb*16 + gid + half*8;
                int hrow = m >> 6, w = m & 63;
                size_t pos = ((size_t)((d0*G + h0 + hrow)*G + w))*64 + n;
                float v0 = fmaxf(acc[mb][nb][half*2+0] + bb.x, 0.f);
                float v1 = fmaxf(acc[mb][nb][half*2+1] + bb.y, 0.f);
                if (SPLIT_OUT) {
                    unsigned hp, lp;
                    split_pack2(v0, v1, hp, lp);
                    *(unsigned*)(outH + pos) = hp;
                    *(unsigned*)(outL + pos) = lp;
                } else {
                    *(float2*)(outF + pos) = make_float2(v0, v1);
                }
            }
        }
}

// ---------------- launch -----------------------------------------------------
extern "C" void kernel_launch(void* const* d_in, const int* in_sizes, int n_in,
                              void* d_out, int out_size)
{
    const float* pos = (const float*)d_in[0];
    const int*   pts = (const int*)d_in[1];
    const float* W1  = (const float*)d_in[2];
    const float* b1  = (const float*)d_in[3];
    const float* W2  = (const float*)d_in[4];
    const float* b2  = (const float*)d_in[5];
    const float* Wk1 = (const float*)d_in[6];
    const float* bk1 = (const float*)d_in[7];
    const float* Wk2 = (const float*)d_in[8];
    const float* bk2 = (const float*)d_in[9];
    const float* Cw1 = (const float*)d_in[10];
    const float* Cb1 = (const float*)d_in[11];
    const float* Cw2 = (const float*)d_in[12];
    const float* Cb2 = (const float*)d_in[13];
    float* out = (float*)d_out;

    void *pSums, *pCnt, *pYh, *pYl, *pW1h, *pW1l, *pW2h, *pW2l;
    cudaGetSymbolAddress(&pSums, g_sums);
    cudaGetSymbolAddress(&pCnt,  g_cnt);
    cudaGetSymbolAddress(&pYh,   g_yh);
    cudaGetSymbolAddress(&pYl,   g_yl);
    cudaGetSymbolAddress(&pW1h,  g_w1h);
    cudaGetSymbolAddress(&pW1l,  g_w1l);
    cudaGetSymbolAddress(&pW2h,  g_w2h);
    cudaGetSymbolAddress(&pW2l,  g_w2l);

    cudaFuncSetAttribute(mlp_tc, cudaFuncAttributeMaxDynamicSharedMemorySize, MLP_SMEM);
    cudaFuncSetAttribute(conv_mma<true,true>,   cudaFuncAttributeMaxDynamicSharedMemorySize, CONV_SMEM);
    cudaFuncSetAttribute(conv_mma<false,false>, cudaFuncAttributeMaxDynamicSharedMemorySize, CONV_SMEM);

    cudaMemsetAsync(pSums, 0, sizeof(float) * (size_t)S * L);
    cudaMemsetAsync(pCnt,  0, sizeof(float) * (size_t)S);

    repack_all<<<880, 256>>>(Cw1, Cw2, W2);
    mlp_tc<<<NPTS/16, 256, MLP_SMEM>>>(pos, pts, W1, b1, b2, Wk1, bk1, Wk2, bk2);
    conv_mma<true,true><<<2048, 128, CONV_SMEM>>>(
        nullptr, nullptr, (const float*)pSums, (const float*)pCnt,
        (const __nv_bfloat16*)pW1h, (const __nv_bfloat16*)pW1l, Cb1,
        nullptr, (__nv_bfloat16*)pYh, (__nv_bfloat16*)pYl);
    conv_mma<false,false><<<2048, 128, CONV_SMEM>>>(
        (const __nv_bfloat16*)pYh, (const __nv_bfloat16*)pYl, nullptr, nullptr,
        (const __nv_bfloat16*)pW2h, (const __nv_bfloat16*)pW2l, Cb2,
        out, nullptr, nullptr);
}

// round 8
// speedup vs baseline: 3.8735x; 1.0751x over previous
#include <cuda_runtime.h>
#include <cuda_bf16.h>

#define G 64
#define S (G*G*G)
#define L 64
#define NPTS 150000
#define PADW 72                      // padded row stride (144B): ldmatrix conflict-free

// ---------------- scratch (device globals; no allocation allowed) ----------
__device__ float g_sums[S*L];                                  // 67 MB
__device__ float g_cnt[S];                                     // 1 MB
__device__ __align__(16) __nv_bfloat16 g_yh[S*L], g_yl[S*L];   // conv1 out hi/lo
__device__ __align__(16) __nv_bfloat16 g_w1h[27*L*L], g_w1l[27*L*L];  // [t][o][i]
__device__ __align__(16) __nv_bfloat16 g_w2h[27*L*L], g_w2l[27*L*L];
__device__ __align__(16) __nv_bfloat16 g_w2th[L*L], g_w2tl[L*L];      // W2^T [o][l]

__device__ __forceinline__ unsigned pack_bf2(__nv_bfloat16 a, __nv_bfloat16 b) {
    return ((unsigned)__bfloat16_as_ushort(b) << 16) | (unsigned)__bfloat16_as_ushort(a);
}
__device__ __forceinline__ void split_pack2(float a, float b, unsigned& h, unsigned& l) {
    __nv_bfloat16 ah = __float2bfloat16(a), bh = __float2bfloat16(b);
    __nv_bfloat16 al = __float2bfloat16(a - __bfloat162float(ah));
    __nv_bfloat16 bl = __float2bfloat16(b - __bfloat162float(bh));
    h = pack_bf2(ah, bh); l = pack_bf2(al, bl);
}
__device__ __forceinline__ void ldsm4(unsigned addr, unsigned& r0, unsigned& r1,
                                      unsigned& r2, unsigned& r3) {
    asm volatile("ldmatrix.sync.aligned.m8n8.x4.shared.b16 {%0,%1,%2,%3}, [%4];"
        : "=r"(r0), "=r"(r1), "=r"(r2), "=r"(r3) : "r"(addr));
}
__device__ __forceinline__ void mma16816(float* c, const unsigned* a,
                                         unsigned b0, unsigned b1) {
    asm volatile("mma.sync.aligned.m16n8k16.row.col.f32.bf16.bf16.f32 "
        "{%0,%1,%2,%3}, {%4,%5,%6,%7}, {%8,%9}, {%0,%1,%2,%3};"
        : "+f"(c[0]), "+f"(c[1]), "+f"(c[2]), "+f"(c[3])
        : "r"(a[0]), "r"(a[1]), "r"(a[2]), "r"(a[3]), "r"(b0), "r"(b1));
}
__device__ __forceinline__ void cp16(unsigned dst, const void* src) {
    asm volatile("cp.async.cg.shared.global [%0], [%1], 16;" :: "r"(dst), "l"(src));
}
#define CP_COMMIT() asm volatile("cp.async.commit_group;" ::: "memory")
#define CP_WAIT(n)  asm volatile("cp.async.wait_group %0;" :: "n"(n) : "memory")

// ---------------- combined repack: conv weights [t][o][i] + W2^T, hi/lo -----
__global__ void repack_all(const float* __restrict__ Cw1,
                           const float* __restrict__ Cw2,
                           const float* __restrict__ W2) {
    int b = blockIdx.x;
    if (b < 864) {
        int idx = (b % 432) * 256 + threadIdx.x;
        if (idx >= 27*64*64) return;
        int t = idx >> 12, r = idx & 4095;
        int o = r >> 6, i = r & 63;
        const float* src = (b < 432) ? Cw1 : Cw2;
        float v = src[(o*64 + i)*27 + t];
        __nv_bfloat16 h = __float2bfloat16(v);
        __nv_bfloat16 l = __float2bfloat16(v - __bfloat162float(h));
        if (b < 432) { g_w1h[idx] = h; g_w1l[idx] = l; }
        else         { g_w2h[idx] = h; g_w2l[idx] = l; }
    } else {
        int idx = (b - 864) * 256 + threadIdx.x;   // o = idx>>6, l = idx&63
        int o = idx >> 6, l = idx & 63;
        float v = W2[l*64 + o];
        __nv_bfloat16 h = __float2bfloat16(v);
        g_w2th[idx] = h;
        g_w2tl[idx] = __float2bfloat16(v - __bfloat162float(h));
    }
}

// ---------------- tensor-core point MLP + atomic scatter (R6, proven) -------
#define MA_BYTES (2*128*PADW*2)          // 36864 (reused for feat fp32 [128][66])
#define MW_BYTES (2*64*PADW*2)           // 18432
#define MC_OFF   (MA_BYTES + MW_BYTES)   // 55296
#define MLP_SMEM (MC_OFF + 3328)

__global__ void __launch_bounds__(256) mlp_tc(
    const float* __restrict__ pos, const int* __restrict__ pts,
    const float* __restrict__ W1, const float* __restrict__ b1,
    const float* __restrict__ b2,
    const float* __restrict__ Wk1, const float* __restrict__ bk1,
    const float* __restrict__ Wk2, const float* __restrict__ bk2)
{
    extern __shared__ __align__(16) char sm[];
    __nv_bfloat16* smA = (__nv_bfloat16*)sm;               // [hl][128][PADW]
    __nv_bfloat16* smB = (__nv_bfloat16*)(sm + MA_BYTES);  // [hl][64 o][PADW]
    float* smC   = (float*)(sm + MC_OFF);
    float* pos_s = smC;
    float* W1s   = smC + 384;
    float* b1s   = smC + 576;
    float* b2s   = smC + 640;
    float* Wk1s  = smC + 704;
    float* bk1s  = smC + 768;
    float* Wk2s  = smC + 776;
    float* bk2s  = smC + 784;
    int*   cell_s = (int*)(smC + 788);
    float* feat_s = (float*)sm;    // [128][66] fp32, reuses A region after MMA

    const unsigned Abase = (unsigned)__cvta_generic_to_shared(smA);
    const unsigned Bbase = (unsigned)__cvta_generic_to_shared(smB);
    const int tid = threadIdx.x, wid = tid >> 5, lane = tid & 31;
    const int p0 = blockIdx.x * 16;

    {
        int i = tid;        if (i < 384) pos_s[i] = pos[(size_t)p0*24 + i];
        i = tid + 256;      if (i < 384) pos_s[i] = pos[(size_t)p0*24 + i];
        if (tid < 192) W1s[tid] = W1[tid];
        if (tid < 64)  { b1s[tid] = b1[tid]; b2s[tid] = b2[tid]; Wk1s[tid] = Wk1[tid]; }
        if (tid < 8)   { bk1s[tid] = bk1[tid]; Wk2s[tid] = Wk2[tid]; }
        if (tid == 0)  bk2s[0] = bk2[0];
        if (tid < 16) {
            int p = p0 + tid;
            cell_s[tid] = (pts[p*3]*G + pts[p*3+1])*G + pts[p*3+2];
        }
        for (int idx = tid; idx < 1024; idx += 256) {
            int row = idx >> 3, ch = idx & 7;
            int hl = row >> 6, o = row & 63;
            const __nv_bfloat16* s = (hl ? g_w2tl : g_w2th) + o*64 + ch*8;
            *(float4*)(smB + (hl*64 + o)*PADW + ch*8) = *(const float4*)s;
        }
    }
    __syncthreads();

    {
        int r = tid >> 1, l0 = (tid & 1) * 32;
        int p = r >> 3, k = r & 7;
        float px = pos_s[p*24 + k*3 + 0];
        float py = pos_s[p*24 + k*3 + 1];
        float pz = pos_s[p*24 + k*3 + 2];
        unsigned* dH = (unsigned*)(smA + r*PADW + l0);
        unsigned* dL = (unsigned*)(smA + (128 + r)*PADW + l0);
        #pragma unroll
        for (int j = 0; j < 16; ++j) {
            int l = l0 + j*2;
            float v0 = px*W1s[l]   + py*W1s[64+l]   + pz*W1s[128+l]   + b1s[l];
            float v1 = px*W1s[l+1] + py*W1s[64+l+1] + pz*W1s[128+l+1] + b1s[l+1];
            v0 = v0 >= 0.f ? v0 : 0.01f*v0;
            v1 = v1 >= 0.f ? v1 : 0.01f*v1;
            unsigned hp, lp;
            split_pack2(v0, v1, hp, lp);
            dH[j] = hp; dL[j] = lp;
        }
    }
    __syncthreads();

    const int warp_m = wid & 3, warp_n = wid >> 2;
    const int t8 = lane >> 3, lr = lane & 7;
    unsigned aOff[2][2], bOff[2][2];
    #pragma unroll
    for (int hl = 0; hl < 2; ++hl) {
        #pragma unroll
        for (int mb = 0; mb < 2; ++mb) {
            int r = warp_m*32 + mb*16 + (t8 & 1)*8 + lr;
            aOff[hl][mb] = (unsigned)(((hl*128 + r)*PADW + (t8 >> 1)*8) * 2);
        }
        #pragma unroll
        for (int pr = 0; pr < 2; ++pr) {
            int n = warp_n*32 + pr*16 + (t8 >> 1)*8 + lr;
            bOff[hl][pr] = (unsigned)(((hl*64 + n)*PADW + (t8 & 1)*8) * 2);
        }
    }
    float acc[2][4][4];
    #pragma unroll
    for (int mb = 0; mb < 2; ++mb)
        #pragma unroll
        for (int nb = 0; nb < 4; ++nb)
            #pragma unroll
            for (int q = 0; q < 4; ++q) acc[mb][nb][q] = 0.f;

    #pragma unroll
    for (int k0 = 0; k0 < 64; k0 += 16) {
        unsigned ah[2][4], al[2][4], bh[2][4], bl[2][4];
        #pragma unroll
        for (int mb = 0; mb < 2; ++mb) {
            ldsm4(Abase + aOff[0][mb] + k0*2, ah[mb][0], ah[mb][1], ah[mb][2], ah[mb][3]);
            ldsm4(Abase + aOff[1][mb] + k0*2, al[mb][0], al[mb][1], al[mb][2], al[mb][3]);
        }
        #pragma unroll
        for (int pr = 0; pr < 2; ++pr) {
            ldsm4(Bbase + bOff[0][pr] + k0*2, bh[pr][0], bh[pr][1], bh[pr][2], bh[pr][3]);
            ldsm4(Bbase + bOff[1][pr] + k0*2, bl[pr][0], bl[pr][1], bl[pr][2], bl[pr][3]);
        }
        #pragma unroll
        for (int mb = 0; mb < 2; ++mb)
            #pragma unroll
            for (int nb = 0; nb < 4; ++nb) {
                int pr = nb >> 1, sel = (nb & 1) << 1;
                mma16816(acc[mb][nb], ah[mb], bh[pr][sel], bh[pr][sel+1]);
                mma16816(acc[mb][nb], ah[mb], bl[pr][sel], bl[pr][sel+1]);
                mma16816(acc[mb][nb], al[mb], bh[pr][sel], bh[pr][sel+1]);
            }
    }
    __syncthreads();

    {
        const int gid = lane >> 2, qid = lane & 3;
        #pragma unroll
        for (int mb = 0; mb < 2; ++mb)
            #pragma unroll
            for (int nb = 0; nb < 4; ++nb) {
                int n = warp_n*32 + nb*8 + qid*2;
                float2 bb = *(const float2*)&b2s[n];
                #pragma unroll
                for (int half = 0; half < 2; ++half) {
                    int m = warp_m*32 + mb*16 + gid + half*8;
                    *(float2*)&feat_s[m*66 + n] =
                        make_float2(acc[mb][nb][half*2+0] + bb.x,
                                    acc[mb][nb][half*2+1] + bb.y);
                }
            }
    }
    __syncthreads();

    #pragma unroll
    for (int rep = 0; rep < 4; ++rep) {
        int idx = rep*256 + tid;
        int p = idx >> 6, l = idx & 63;
        float f[8];
        #pragma unroll
        for (int k = 0; k < 8; ++k) f[k] = feat_s[(p*8 + k)*66 + l];
        float f2 = bk2s[0];
        #pragma unroll
        for (int o = 0; o < 8; ++o) {
            float s = bk1s[o];
            #pragma unroll
            for (int k = 0; k < 8; ++k) s += Wk1s[o*8 + k] * f[k];
            s = s >= 0.f ? s : 0.01f*s;
            f2 += Wk2s[o] * s;
        }
        int cell = cell_s[p];
        atomicAdd(&g_sums[(size_t)cell*64 + l], f2);
        if (l == 0) atomicAdd(&g_cnt[cell], 1.0f);
    }
}

// ---------------- mma.sync conv3d — cp.async double-buffered weights --------
// CTA: 2 h-rows x 64 w (M=128) x 64 out-ch (N=64); 4 warps, warp tile 64x32.
// Uniform 27-tap loop (A zero-filled when dd OOB); W[t+1] prefetched via
// cp.async while tap t computes.
#define A_ELEMS (2*2*66*PADW)                 // 19008 elems
#define A_BYTES (A_ELEMS*2)                   // 38016 B
#define WBUF_BYTES (2*64*PADW*2)              // 18432 B per stage
#define CONV_SMEM (A_BYTES + 2*WBUF_BYTES)    // 74880 B -> 3 CTAs/SM

template<bool SPLIT_OUT, bool READ_F32>
__global__ void __launch_bounds__(128, 3) conv_mma(
    const __nv_bfloat16* __restrict__ xh, const __nv_bfloat16* __restrict__ xl,
    const float* __restrict__ xf, const float* __restrict__ xcnt,
    const __nv_bfloat16* __restrict__ wth, const __nv_bfloat16* __restrict__ wtl,
    const float* __restrict__ bias,
    float* __restrict__ outF,
    __nv_bfloat16* __restrict__ outH, __nv_bfloat16* __restrict__ outL)
{
    extern __shared__ __align__(16) char sm_raw[];
    __nv_bfloat16* smA = (__nv_bfloat16*)sm_raw;                 // [hl][hrow][66][PADW]
    const unsigned Abase = (unsigned)__cvta_generic_to_shared(smA);
    const unsigned Wbase0 = Abase + A_BYTES;                     // 2 W stages

    const int tid = threadIdx.x;
    const int wid = tid >> 5, lane = tid & 31;
    const int d0 = blockIdx.x >> 5;
    const int h0 = (blockIdx.x & 31) << 1;
    const int warp_m = wid & 1, warp_n = wid >> 1;   // m0 = warp_m*64, n0 = warp_n*32

    const int t8 = lane >> 3, lr = lane & 7;
    unsigned aOff[2][4], bOff[2][2];
    #pragma unroll
    for (int hl = 0; hl < 2; ++hl) {
        #pragma unroll
        for (int mb = 0; mb < 4; ++mb) {
            int r = warp_m*64 + mb*16 + (t8 & 1)*8 + lr;
            int hrow = r >> 6, w = r & 63;
            aOff[hl][mb] = (unsigned)((((hl*2 + hrow)*66 + w)*PADW + (t8 >> 1)*8) * 2);
        }
        #pragma unroll
        for (int pr = 0; pr < 2; ++pr) {
            int n = warp_n*32 + pr*16 + (t8 >> 1)*8 + lr;
            bOff[hl][pr] = (unsigned)(((hl*64 + n)*PADW + (t8 & 1)*8) * 2);
        }
    }

    float acc[4][4][4];
    #pragma unroll
    for (int mb = 0; mb < 4; ++mb)
        #pragma unroll
        for (int nb = 0; nb < 4; ++nb)
            #pragma unroll
            for (int q = 0; q < 4; ++q) acc[mb][nb][q] = 0.f;

    // W prefetch: 1024 16B chunks, 8 per thread, own cp.async group
    auto issueW = [&](int tap, int buf) {
        unsigned wdst = Wbase0 + (unsigned)buf * WBUF_BYTES;
        #pragma unroll
        for (int i = 0; i < 8; ++i) {
            int idx = tid + i*128;
            int row = idx >> 3, cch = idx & 7;
            int hl = row >> 6, o = row & 63;
            const __nv_bfloat16* s = (hl ? wtl : wth) + ((size_t)tap*4096 + o*64 + cch*8);
            cp16(wdst + (unsigned)((hl*64 + o)*PADW + cch*8)*2, s);
        }
        CP_COMMIT();
    };

    issueW(0, 0);

    for (int dzy = 0; dzy < 9; ++dzy) {
        const int dz = dzy / 3, dy = dzy % 3;
        const int dd = d0 + dz - 1;
        const bool dValid = (unsigned)dd < (unsigned)G;

        __syncthreads();   // all reads of previous A and previous-W buffer done
        // ---- A stage ----
        if (READ_F32) {
            for (int task = tid; task < 256; task += 128) {
                const int hrA = task >> 7;
                const int wA2 = (task >> 1) & 63;
                const int cH = task & 1;
                const int hin = h0 + dy - 1 + hrA;
                uint2* dH = (uint2*)(smA + ((0 + hrA)*66 + wA2 + 1)*PADW + cH*32);
                uint2* dL = (uint2*)(smA + ((2 + hrA)*66 + wA2 + 1)*PADW + cH*32);
                if (dValid && (unsigned)hin < (unsigned)G) {
                    size_t cell = (size_t)(dd*G + hin)*G + wA2;
                    float c = xcnt[cell];
                    float inv = c > 0.f ? 1.f/c : 0.f;
                    const float4* s4 = (const float4*)(xf + cell*64 + cH*32);
                    #pragma unroll
                    for (int j = 0; j < 8; ++j) {
                        float4 v = s4[j];
                        unsigned hp0, lp0, hp1, lp1;
                        split_pack2(v.x*inv, v.y*inv, hp0, lp0);
                        split_pack2(v.z*inv, v.w*inv, hp1, lp1);
                        dH[j] = make_uint2(hp0, hp1);
                        dL[j] = make_uint2(lp0, lp1);
                    }
                } else {
                    uint2 z = make_uint2(0u, 0u);
                    #pragma unroll
                    for (int j = 0; j < 8; ++j) { dH[j] = z; dL[j] = z; }
                }
                if (wA2 == 0) {
                    uint2 z = make_uint2(0u, 0u);
                    uint2* zh = (uint2*)(smA + ((0 + hrA)*66)*PADW + cH*32);
                    uint2* zl = (uint2*)(smA + ((2 + hrA)*66)*PADW + cH*32);
                    #pragma unroll
                    for (int j = 0; j < 8; ++j) { zh[j] = z; zl[j] = z; }
                }
                if (wA2 == 63) {
                    uint2 z = make_uint2(0u, 0u);
                    uint2* zh = (uint2*)(smA + ((0 + hrA)*66 + 65)*PADW + cH*32);
                    uint2* zl = (uint2*)(smA + ((2 + hrA)*66 + 65)*PADW + cH*32);
                    #pragma unroll
                    for (int j = 0; j < 8; ++j) { zh[j] = z; zl[j] = z; }
                }
            }
        } else {
            for (int task = tid; task < 256; task += 128) {
                const int gA = task >> 6, hlA = gA >> 1, hrA = gA & 1, wA = task & 63;
                const int hin = h0 + dy - 1 + hrA;
                unsigned dstU = Abase + (unsigned)(((hlA*2 + hrA)*66 + wA + 1)*PADW)*2;
                if (dValid && (unsigned)hin < (unsigned)G) {
                    const __nv_bfloat16* src = (hlA ? xl : xh) +
                        (((size_t)(dd*G + hin))*G + wA) * 64;
                    #pragma unroll
                    for (int j = 0; j < 8; ++j) cp16(dstU + j*16, src + j*8);
                } else {
                    float4 z = make_float4(0.f, 0.f, 0.f, 0.f);
                    float4* d4 = (float4*)(smA + ((hlA*2 + hrA)*66 + wA + 1)*PADW);
                    #pragma unroll
                    for (int j = 0; j < 8; ++j) d4[j] = z;
                }
                if (wA == 0) {
                    float4 z = make_float4(0.f, 0.f, 0.f, 0.f);
                    float4* h4 = (float4*)(smA + ((hlA*2 + hrA)*66)*PADW);
                    #pragma unroll
                    for (int j = 0; j < 8; ++j) h4[j] = z;
                }
                if (wA == 63) {
                    float4 z = make_float4(0.f, 0.f, 0.f, 0.f);
                    float4* h4 = (float4*)(smA + ((hlA*2 + hrA)*66 + 65)*PADW);
                    #pragma unroll
                    for (int j = 0; j < 8; ++j) h4[j] = z;
                }
            }
            CP_COMMIT();   // A group (bf16 path)
        }

        for (int dx = 0; dx < 3; ++dx) {
            const int t = dzy*3 + dx;
            if (dx != 0) __syncthreads();          // reads of W[t-1] done
            if (t < 26) issueW(t + 1, (t + 1) & 1);
            if (t < 26) { CP_WAIT(1); } else { CP_WAIT(0); }   // W[t] (+A) landed
            __syncthreads();                        // completion visible CTA-wide

            const unsigned Adx = Abase + (unsigned)(dx * PADW * 2);
            const unsigned Wb = Wbase0 + (unsigned)(t & 1) * WBUF_BYTES;
            #pragma unroll
            for (int k0 = 0; k0 < 64; k0 += 16) {
                unsigned bh[2][4], bl[2][4];
                #pragma unroll
                for (int pr = 0; pr < 2; ++pr) {
                    ldsm4(Wb + bOff[0][pr] + k0*2, bh[pr][0], bh[pr][1], bh[pr][2], bh[pr][3]);
                    ldsm4(Wb + bOff[1][pr] + k0*2, bl[pr][0], bl[pr][1], bl[pr][2], bl[pr][3]);
                }
                #pragma unroll
                for (int mb = 0; mb < 4; ++mb) {
                    unsigned ah[4], al[4];
                    ldsm4(Adx + aOff[0][mb] + k0*2, ah[0], ah[1], ah[2], ah[3]);
                    ldsm4(Adx + aOff[1][mb] + k0*2, al[0], al[1], al[2], al[3]);
                    #pragma unroll
                    for (int nb = 0; nb < 4; ++nb) {
                        int pr = nb >> 1, sel = (nb & 1) << 1;
                        mma16816(acc[mb][nb], ah, bh[pr][sel], bh[pr][sel+1]);
                        mma16816(acc[mb][nb], ah, bl[pr][sel], bl[pr][sel+1]);
                        mma16816(acc[mb][nb], al, bh[pr][sel], bh[pr][sel+1]);
                    }
                }
            }
        }
    }

    const int gid = lane >> 2, qid = lane & 3;
    #pragma unroll
    for (int mb = 0; mb < 4; ++mb)
        #pragma unroll
        for (int nb = 0; nb < 4; ++nb) {
            int n = warp_n*32 + nb*8 + qid*2;
            float2 bb = *(const float2*)&bias[n];
            #pragma unroll
            for (int half = 0; half < 2; ++half) {
                int m = warp_m*64 + mb*16 + gid + half*8;
                int hrow = m >> 6, w = m & 63;
                size_t pos = ((size_t)((d0*G + h0 + hrow)*G + w))*64 + n;
                float v0 = fmaxf(acc[mb][nb][half*2+0] + bb.x, 0.f);
                float v1 = fmaxf(acc[mb][nb][half*2+1] + bb.y, 0.f);
                if (SPLIT_OUT) {
                    unsigned hp, lp;
                    split_pack2(v0, v1, hp, lp);
                    *(unsigned*)(outH + pos) = hp;
                    *(unsigned*)(outL + pos) = lp;
                } else {
                    *(float2*)(outF + pos) = make_float2(v0, v1);
                }
            }
        }
}

// ---------------- launch -----------------------------------------------------
extern "C" void kernel_launch(void* const* d_in, const int* in_sizes, int n_in,
                              void* d_out, int out_size)
{
    const float* pos = (const float*)d_in[0];
    const int*   pts = (const int*)d_in[1];
    const float* W1  = (const float*)d_in[2];
    const float* b1  = (const float*)d_in[3];
    const float* W2  = (const float*)d_in[4];
    const float* b2  = (const float*)d_in[5];
    const float* Wk1 = (const float*)d_in[6];
    const float* bk1 = (const float*)d_in[7];
    const float* Wk2 = (const float*)d_in[8];
    const float* bk2 = (const float*)d_in[9];
    const float* Cw1 = (const float*)d_in[10];
    const float* Cb1 = (const float*)d_in[11];
    const float* Cw2 = (const float*)d_in[12];
    const float* Cb2 = (const float*)d_in[13];
    float* out = (float*)d_out;

    void *pSums, *pCnt, *pYh, *pYl, *pW1h, *pW1l, *pW2h, *pW2l;
    cudaGetSymbolAddress(&pSums, g_sums);
    cudaGetSymbolAddress(&pCnt,  g_cnt);
    cudaGetSymbolAddress(&pYh,   g_yh);
    cudaGetSymbolAddress(&pYl,   g_yl);
    cudaGetSymbolAddress(&pW1h,  g_w1h);
    cudaGetSymbolAddress(&pW1l,  g_w1l);
    cudaGetSymbolAddress(&pW2h,  g_w2h);
    cudaGetSymbolAddress(&pW2l,  g_w2l);

    cudaFuncSetAttribute(mlp_tc, cudaFuncAttributeMaxDynamicSharedMemorySize, MLP_SMEM);
    cudaFuncSetAttribute(conv_mma<true,true>,   cudaFuncAttributeMaxDynamicSharedMemorySize, CONV_SMEM);
    cudaFuncSetAttribute(conv_mma<false,false>, cudaFuncAttributeMaxDynamicSharedMemorySize, CONV_SMEM);

    cudaMemsetAsync(pSums, 0, sizeof(float) * (size_t)S * L);
    cudaMemsetAsync(pCnt,  0, sizeof(float) * (size_t)S);

    repack_all<<<880, 256>>>(Cw1, Cw2, W2);
    mlp_tc<<<NPTS/16, 256, MLP_SMEM>>>(pos, pts, W1, b1, b2, Wk1, bk1, Wk2, bk2);
    conv_mma<true,true><<<2048, 128, CONV_SMEM>>>(
        nullptr, nullptr, (const float*)pSums, (const float*)pCnt,
        (const __nv_bfloat16*)pW1h, (const __nv_bfloat16*)pW1l, Cb1,
        nullptr, (__nv_bfloat16*)pYh, (__nv_bfloat16*)pYl);
    conv_mma<false,false><<<2048, 128, CONV_SMEM>>>(
        (const __nv_bfloat16*)pYh, (const __nv_bfloat16*)pYl, nullptr, nullptr,
        (const __nv_bfloat16*)pW2h, (const __nv_bfloat16*)pW2l, Cb2,
        out, nullptr, nullptr);
}

// round 9
// speedup vs baseline: 4.0577x; 1.0475x over previous
#include <cuda_runtime.h>
#include <cuda_bf16.h>

#define G 64
#define S (G*G*G)
#define L 64
#define NPTS 150000
#define PADW 72                      // padded channel stride (144B): ldmatrix conflict-free

// ---------------- scratch (device globals; no allocation allowed) ----------
__device__ float g_sums[S*L];                                  // 67 MB
__device__ float g_cnt[S];                                     // 1 MB
__device__ __align__(16) __nv_bfloat16 g_yh[S*L], g_yl[S*L];   // conv1 out hi/lo
// conv weights in mma-fragment order:
// idx = ((((t*2+wn)*2+hl)*2+pr)*4+q)*32 + lane   (uint4 units)
__device__ __align__(16) uint4 g_wf1[27648], g_wf2[27648];
__device__ __align__(16) __nv_bfloat16 g_w2th[L*L], g_w2tl[L*L];      // W2^T [o][l]

__device__ __forceinline__ unsigned pack_bf2(__nv_bfloat16 a, __nv_bfloat16 b) {
    return ((unsigned)__bfloat16_as_ushort(b) << 16) | (unsigned)__bfloat16_as_ushort(a);
}
__device__ __forceinline__ void split_pack2(float a, float b, unsigned& h, unsigned& l) {
    __nv_bfloat16 ah = __float2bfloat16(a), bh = __float2bfloat16(b);
    __nv_bfloat16 al = __float2bfloat16(a - __bfloat162float(ah));
    __nv_bfloat16 bl = __float2bfloat16(b - __bfloat162float(bh));
    h = pack_bf2(ah, bh); l = pack_bf2(al, bl);
}
__device__ __forceinline__ void ldsm4(unsigned addr, unsigned& r0, unsigned& r1,
                                      unsigned& r2, unsigned& r3) {
    asm volatile("ldmatrix.sync.aligned.m8n8.x4.shared.b16 {%0,%1,%2,%3}, [%4];"
        : "=r"(r0), "=r"(r1), "=r"(r2), "=r"(r3) : "r"(addr));
}
__device__ __forceinline__ void mma16816(float* c, const unsigned* a,
                                         unsigned b0, unsigned b1) {
    asm volatile("mma.sync.aligned.m16n8k16.row.col.f32.bf16.bf16.f32 "
        "{%0,%1,%2,%3}, {%4,%5,%6,%7}, {%8,%9}, {%0,%1,%2,%3};"
        : "+f"(c[0]), "+f"(c[1]), "+f"(c[2]), "+f"(c[3])
        : "r"(a[0]), "r"(a[1]), "r"(a[2]), "r"(a[3]), "r"(b0), "r"(b1));
}
__device__ __forceinline__ void cp16(unsigned dst, const void* src) {
    asm volatile("cp.async.cg.shared.global [%0], [%1], 16;" :: "r"(dst), "l"(src));
}
#define CP_COMMIT() asm volatile("cp.async.commit_group;" ::: "memory")
#define CP_WAIT(n)  asm volatile("cp.async.wait_group %0;" :: "n"(n) : "memory")

// ---------------- repack: conv weights -> mma fragment order; W2^T ----------
// B fragment (ldmatrix.x4 on [o][i] rows): reg j of lane l =
//   W[o = wn*32 + pr*16 + (j>>1)*8 + (l>>2)][i = q*16 + (j&1)*8 + (l&3)*2 + {0,1}]
__global__ void repack_all(const float* __restrict__ Cw1,
                           const float* __restrict__ Cw2,
                           const float* __restrict__ W2) {
    int b = blockIdx.x;
    if (b < 216) {
        int idx = b*256 + threadIdx.x;          // 0..55295
        if (idx >= 55296) return;
        int conv = idx >= 27648;
        int r = conv ? idx - 27648 : idx;
        int lane = r & 31;
        int q  = (r >> 5) & 3;
        int pr = (r >> 7) & 1;
        int hl = (r >> 8) & 1;
        int wn = (r >> 9) & 1;
        int t  = r >> 10;                        // 0..26
        const float* src = conv ? Cw2 : Cw1;
        unsigned comp[4];
        #pragma unroll
        for (int j = 0; j < 4; ++j) {
            int o  = wn*32 + pr*16 + (j >> 1)*8 + (lane >> 2);
            int i0 = q*16 + (j & 1)*8 + (lane & 3)*2;
            float v0 = src[(o*64 + i0)*27 + t];
            float v1 = src[(o*64 + i0 + 1)*27 + t];
            __nv_bfloat16 h0 = __float2bfloat16(v0), h1 = __float2bfloat16(v1);
            if (hl == 0) {
                comp[j] = pack_bf2(h0, h1);
            } else {
                __nv_bfloat16 l0 = __float2bfloat16(v0 - __bfloat162float(h0));
                __nv_bfloat16 l1 = __float2bfloat16(v1 - __bfloat162float(h1));
                comp[j] = pack_bf2(l0, l1);
            }
        }
        uint4 u = make_uint4(comp[0], comp[1], comp[2], comp[3]);
        if (conv) g_wf2[r] = u; else g_wf1[r] = u;
    } else {
        int idx = (b - 216)*256 + threadIdx.x;   // 0..4095
        if (idx >= 4096) return;
        int o = idx >> 6, l = idx & 63;
        float v = W2[l*64 + o];
        __nv_bfloat16 h = __float2bfloat16(v);
        g_w2th[idx] = h;
        g_w2tl[idx] = __float2bfloat16(v - __bfloat162float(h));
    }
}

// ---------------- tensor-core point MLP + atomic scatter (R6, proven) -------
#define MA_BYTES (2*128*PADW*2)
#define MW_BYTES (2*64*PADW*2)
#define MC_OFF   (MA_BYTES + MW_BYTES)
#define MLP_SMEM (MC_OFF + 3328)

__global__ void __launch_bounds__(256) mlp_tc(
    const float* __restrict__ pos, const int* __restrict__ pts,
    const float* __restrict__ W1, const float* __restrict__ b1,
    const float* __restrict__ b2,
    const float* __restrict__ Wk1, const float* __restrict__ bk1,
    const float* __restrict__ Wk2, const float* __restrict__ bk2)
{
    extern __shared__ __align__(16) char sm[];
    __nv_bfloat16* smA = (__nv_bfloat16*)sm;
    __nv_bfloat16* smB = (__nv_bfloat16*)(sm + MA_BYTES);
    float* smC   = (float*)(sm + MC_OFF);
    float* pos_s = smC;
    float* W1s   = smC + 384;
    float* b1s   = smC + 576;
    float* b2s   = smC + 640;
    float* Wk1s  = smC + 704;
    float* bk1s  = smC + 768;
    float* Wk2s  = smC + 776;
    float* bk2s  = smC + 784;
    int*   cell_s = (int*)(smC + 788);
    float* feat_s = (float*)sm;

    const unsigned Abase = (unsigned)__cvta_generic_to_shared(smA);
    const unsigned Bbase = (unsigned)__cvta_generic_to_shared(smB);
    const int tid = threadIdx.x, wid = tid >> 5, lane = tid & 31;
    const int p0 = blockIdx.x * 16;

    {
        int i = tid;        if (i < 384) pos_s[i] = pos[(size_t)p0*24 + i];
        i = tid + 256;      if (i < 384) pos_s[i] = pos[(size_t)p0*24 + i];
        if (tid < 192) W1s[tid] = W1[tid];
        if (tid < 64)  { b1s[tid] = b1[tid]; b2s[tid] = b2[tid]; Wk1s[tid] = Wk1[tid]; }
        if (tid < 8)   { bk1s[tid] = bk1[tid]; Wk2s[tid] = Wk2[tid]; }
        if (tid == 0)  bk2s[0] = bk2[0];
        if (tid < 16) {
            int p = p0 + tid;
            cell_s[tid] = (pts[p*3]*G + pts[p*3+1])*G + pts[p*3+2];
        }
        for (int idx = tid; idx < 1024; idx += 256) {
            int row = idx >> 3, ch = idx & 7;
            int hl = row >> 6, o = row & 63;
            const __nv_bfloat16* s = (hl ? g_w2tl : g_w2th) + o*64 + ch*8;
            *(float4*)(smB + (hl*64 + o)*PADW + ch*8) = *(const float4*)s;
        }
    }
    __syncthreads();

    {
        int r = tid >> 1, l0 = (tid & 1) * 32;
        int p = r >> 3, k = r & 7;
        float px = pos_s[p*24 + k*3 + 0];
        float py = pos_s[p*24 + k*3 + 1];
        float pz = pos_s[p*24 + k*3 + 2];
        unsigned* dH = (unsigned*)(smA + r*PADW + l0);
        unsigned* dL = (unsigned*)(smA + (128 + r)*PADW + l0);
        #pragma unroll
        for (int j = 0; j < 16; ++j) {
            int l = l0 + j*2;
            float v0 = px*W1s[l]   + py*W1s[64+l]   + pz*W1s[128+l]   + b1s[l];
            float v1 = px*W1s[l+1] + py*W1s[64+l+1] + pz*W1s[128+l+1] + b1s[l+1];
            v0 = v0 >= 0.f ? v0 : 0.01f*v0;
            v1 = v1 >= 0.f ? v1 : 0.01f*v1;
            unsigned hp, lp;
            split_pack2(v0, v1, hp, lp);
            dH[j] = hp; dL[j] = lp;
        }
    }
    __syncthreads();

    const int warp_m = wid & 3, warp_n = wid >> 2;
    const int t8 = lane >> 3, lr = lane & 7;
    unsigned aOff[2][2], bOff[2][2];
    #pragma unroll
    for (int hl = 0; hl < 2; ++hl) {
        #pragma unroll
        for (int mb = 0; mb < 2; ++mb) {
            int r = warp_m*32 + mb*16 + (t8 & 1)*8 + lr;
            aOff[hl][mb] = (unsigned)(((hl*128 + r)*PADW + (t8 >> 1)*8) * 2);
        }
        #pragma unroll
        for (int pr = 0; pr < 2; ++pr) {
            int n = warp_n*32 + pr*16 + (t8 >> 1)*8 + lr;
            bOff[hl][pr] = (unsigned)(((hl*64 + n)*PADW + (t8 & 1)*8) * 2);
        }
    }
    float acc[2][4][4];
    #pragma unroll
    for (int mb = 0; mb < 2; ++mb)
        #pragma unroll
        for (int nb = 0; nb < 4; ++nb)
            #pragma unroll
            for (int q = 0; q < 4; ++q) acc[mb][nb][q] = 0.f;

    #pragma unroll
    for (int k0 = 0; k0 < 64; k0 += 16) {
        unsigned ah[2][4], al[2][4], bh[2][4], bl[2][4];
        #pragma unroll
        for (int mb = 0; mb < 2; ++mb) {
            ldsm4(Abase + aOff[0][mb] + k0*2, ah[mb][0], ah[mb][1], ah[mb][2], ah[mb][3]);
            ldsm4(Abase + aOff[1][mb] + k0*2, al[mb][0], al[mb][1], al[mb][2], al[mb][3]);
        }
        #pragma unroll
        for (int pr = 0; pr < 2; ++pr) {
            ldsm4(Bbase + bOff[0][pr] + k0*2, bh[pr][0], bh[pr][1], bh[pr][2], bh[pr][3]);
            ldsm4(Bbase + bOff[1][pr] + k0*2, bl[pr][0], bl[pr][1], bl[pr][2], bl[pr][3]);
        }
        #pragma unroll
        for (int mb = 0; mb < 2; ++mb)
            #pragma unroll
            for (int nb = 0; nb < 4; ++nb) {
                int pr = nb >> 1, sel = (nb & 1) << 1;
                mma16816(acc[mb][nb], ah[mb], bh[pr][sel], bh[pr][sel+1]);
                mma16816(acc[mb][nb], ah[mb], bl[pr][sel], bl[pr][sel+1]);
                mma16816(acc[mb][nb], al[mb], bh[pr][sel], bh[pr][sel+1]);
            }
    }
    __syncthreads();

    {
        const int gid = lane >> 2, qid = lane & 3;
        #pragma unroll
        for (int mb = 0; mb < 2; ++mb)
            #pragma unroll
            for (int nb = 0; nb < 4; ++nb) {
                int n = warp_n*32 + nb*8 + qid*2;
                float2 bb = *(const float2*)&b2s[n];
                #pragma unroll
                for (int half = 0; half < 2; ++half) {
                    int m = warp_m*32 + mb*16 + gid + half*8;
                    *(float2*)&feat_s[m*66 + n] =
                        make_float2(acc[mb][nb][half*2+0] + bb.x,
                                    acc[mb][nb][half*2+1] + bb.y);
                }
            }
    }
    __syncthreads();

    #pragma unroll
    for (int rep = 0; rep < 4; ++rep) {
        int idx = rep*256 + tid;
        int p = idx >> 6, l = idx & 63;
        float f[8];
        #pragma unroll
        for (int k = 0; k < 8; ++k) f[k] = feat_s[(p*8 + k)*66 + l];
        float f2 = bk2s[0];
        #pragma unroll
        for (int o = 0; o < 8; ++o) {
            float s = bk1s[o];
            #pragma unroll
            for (int k = 0; k < 8; ++k) s += Wk1s[o*8 + k] * f[k];
            s = s >= 0.f ? s : 0.01f*s;
            f2 += Wk2s[o] * s;
        }
        int cell = cell_s[p];
        atomicAdd(&g_sums[(size_t)cell*64 + l], f2);
        if (l == 0) atomicAdd(&g_cnt[cell], 1.0f);
    }
}

// ---------------- mma.sync conv3d — direct-LDG B fragments, A-only smem -----
// CTA: 2 h-rows x 64 w (M=128) x 64 out-ch (N=64); 4 warps, warp tile 64x32.
// Weights read as prebuilt fragments via LDG.128 (L2-resident), register
// double-buffered; only A staging needs barriers (2 per dzy, 18 total).
#define A_ELEMS (2*2*66*PADW)
#define A_BYTES (A_ELEMS*2)                   // 38016 B
#define CONV_SMEM A_BYTES

template<bool SPLIT_OUT, bool READ_F32>
__global__ void __launch_bounds__(128, 3) conv_mma(
    const __nv_bfloat16* __restrict__ xh, const __nv_bfloat16* __restrict__ xl,
    const float* __restrict__ xf, const float* __restrict__ xcnt,
    const uint4* __restrict__ wfrag,
    const float* __restrict__ bias,
    float* __restrict__ outF,
    __nv_bfloat16* __restrict__ outH, __nv_bfloat16* __restrict__ outL)
{
    extern __shared__ __align__(16) char sm_raw[];
    __nv_bfloat16* smA = (__nv_bfloat16*)sm_raw;                 // [hl][hrow][66][PADW]
    const unsigned Abase = (unsigned)__cvta_generic_to_shared(smA);

    const int tid = threadIdx.x;
    const int wid = tid >> 5, lane = tid & 31;
    const int d0 = blockIdx.x >> 5;
    const int h0 = (blockIdx.x & 31) << 1;
    const int warp_m = wid & 1, warp_n = wid >> 1;

    const int t8 = lane >> 3, lr = lane & 7;
    unsigned aOff[2][4];
    #pragma unroll
    for (int hl = 0; hl < 2; ++hl)
        #pragma unroll
        for (int mb = 0; mb < 4; ++mb) {
            int r = warp_m*64 + mb*16 + (t8 & 1)*8 + lr;
            int hrow = r >> 6, w = r & 63;
            aOff[hl][mb] = (unsigned)((((hl*2 + hrow)*66 + w)*PADW + (t8 >> 1)*8) * 2);
        }

    // fragment pointer: + wn*512 + lane; offsets: t*1024 + q*32, hl +256, pr +128
    const uint4* wp = wfrag + warp_n*512 + lane;

    float acc[4][4][4];
    #pragma unroll
    for (int mb = 0; mb < 4; ++mb)
        #pragma unroll
        for (int nb = 0; nb < 4; ++nb)
            #pragma unroll
            for (int q = 0; q < 4; ++q) acc[mb][nb][q] = 0.f;

    // B fragment double buffer: [hl*2+pr]
    uint4 bcur[4], bnxt[4];
    #pragma unroll
    for (int i = 0; i < 4; ++i)
        bcur[i] = wp[(i >> 1)*256 + (i & 1)*128];   // t=0, q=0

    for (int dzy = 0; dzy < 9; ++dzy) {
        const int dz = dzy / 3, dy = dzy % 3;
        const int dd = d0 + dz - 1;
        const bool dValid = (unsigned)dd < (unsigned)G;

        __syncthreads();   // all reads of previous A done
        if (READ_F32) {
            for (int task = tid; task < 256; task += 128) {
                const int hrA = task >> 7;
                const int wA2 = (task >> 1) & 63;
                const int cH = task & 1;
                const int hin = h0 + dy - 1 + hrA;
                uint2* dH = (uint2*)(smA + ((0 + hrA)*66 + wA2 + 1)*PADW + cH*32);
                uint2* dL = (uint2*)(smA + ((2 + hrA)*66 + wA2 + 1)*PADW + cH*32);
                if (dValid && (unsigned)hin < (unsigned)G) {
                    size_t cell = (size_t)(dd*G + hin)*G + wA2;
                    float c = xcnt[cell];
                    float inv = c > 0.f ? 1.f/c : 0.f;
                    const float4* s4 = (const float4*)(xf + cell*64 + cH*32);
                    #pragma unroll
                    for (int j = 0; j < 8; ++j) {
                        float4 v = s4[j];
                        unsigned hp0, lp0, hp1, lp1;
                        split_pack2(v.x*inv, v.y*inv, hp0, lp0);
                        split_pack2(v.z*inv, v.w*inv, hp1, lp1);
                        dH[j] = make_uint2(hp0, hp1);
                        dL[j] = make_uint2(lp0, lp1);
                    }
                } else {
                    uint2 z = make_uint2(0u, 0u);
                    #pragma unroll
                    for (int j = 0; j < 8; ++j) { dH[j] = z; dL[j] = z; }
                }
                if (wA2 == 0) {
                    uint2 z = make_uint2(0u, 0u);
                    uint2* zh = (uint2*)(smA + ((0 + hrA)*66)*PADW + cH*32);
                    uint2* zl = (uint2*)(smA + ((2 + hrA)*66)*PADW + cH*32);
                    #pragma unroll
                    for (int j = 0; j < 8; ++j) { zh[j] = z; zl[j] = z; }
                }
                if (wA2 == 63) {
                    uint2 z = make_uint2(0u, 0u);
                    uint2* zh = (uint2*)(smA + ((0 + hrA)*66 + 65)*PADW + cH*32);
                    uint2* zl = (uint2*)(smA + ((2 + hrA)*66 + 65)*PADW + cH*32);
                    #pragma unroll
                    for (int j = 0; j < 8; ++j) { zh[j] = z; zl[j] = z; }
                }
            }
        } else {
            for (int task = tid; task < 256; task += 128) {
                const int gA = task >> 6, hlA = gA >> 1, hrA = gA & 1, wA = task & 63;
                const int hin = h0 + dy - 1 + hrA;
                unsigned dstU = Abase + (unsigned)(((hlA*2 + hrA)*66 + wA + 1)*PADW)*2;
                if (dValid && (unsigned)hin < (unsigned)G) {
                    const __nv_bfloat16* src = (hlA ? xl : xh) +
                        (((size_t)(dd*G + hin))*G + wA) * 64;
                    #pragma unroll
                    for (int j = 0; j < 8; ++j) cp16(dstU + j*16, src + j*8);
                } else {
                    float4 z = make_float4(0.f, 0.f, 0.f, 0.f);
                    float4* d4 = (float4*)(smA + ((hlA*2 + hrA)*66 + wA + 1)*PADW);
                    #pragma unroll
                    for (int j = 0; j < 8; ++j) d4[j] = z;
                }
                if (wA == 0) {
                    float4 z = make_float4(0.f, 0.f, 0.f, 0.f);
                    float4* h4 = (float4*)(smA + ((hlA*2 + hrA)*66)*PADW);
                    #pragma unroll
                    for (int j = 0; j < 8; ++j) h4[j] = z;
                }
                if (wA == 63) {
                    float4 z = make_float4(0.f, 0.f, 0.f, 0.f);
                    float4* h4 = (float4*)(smA + ((hlA*2 + hrA)*66 + 65)*PADW);
                    #pragma unroll
                    for (int j = 0; j < 8; ++j) h4[j] = z;
                }
            }
            CP_COMMIT();
            CP_WAIT(0);
        }
        __syncthreads();   // A tile visible CTA-wide

        #pragma unroll
        for (int dx = 0; dx < 3; ++dx) {
            const int t = dzy*3 + dx;
            const unsigned Adx = Abase + (unsigned)(dx * PADW * 2);
            #pragma unroll
            for (int q = 0; q < 4; ++q) {
                // prefetch next (t,q) fragment set (wraps to tap 0 at the end)
                int nt = t, nq = q + 1;
                if (nq == 4) { nq = 0; nt = (t == 26) ? 0 : t + 1; }
                const int noff = nt*1024 + nq*32;
                #pragma unroll
                for (int i = 0; i < 4; ++i)
                    bnxt[i] = wp[noff + (i >> 1)*256 + (i & 1)*128];

                #pragma unroll
                for (int mb = 0; mb < 4; ++mb) {
                    unsigned ah[4], al[4];
                    ldsm4(Adx + aOff[0][mb] + q*32, ah[0], ah[1], ah[2], ah[3]);
                    ldsm4(Adx + aOff[1][mb] + q*32, al[0], al[1], al[2], al[3]);
                    #pragma unroll
                    for (int nb = 0; nb < 4; ++nb) {
                        int pr = nb >> 1;
                        const unsigned* BH = (const unsigned*)&bcur[pr];
                        const unsigned* BL = (const unsigned*)&bcur[2 + pr];
                        int sel = (nb & 1) << 1;
                        mma16816(acc[mb][nb], ah, BH[sel], BH[sel+1]);
                        mma16816(acc[mb][nb], ah, BL[sel], BL[sel+1]);
                        mma16816(acc[mb][nb], al, BH[sel], BH[sel+1]);
                    }
                }
                #pragma unroll
                for (int i = 0; i < 4; ++i) bcur[i] = bnxt[i];
            }
        }
    }

    const int gid = lane >> 2, qid = lane & 3;
    #pragma unroll
    for (int mb = 0; mb < 4; ++mb)
        #pragma unroll
        for (int nb = 0; nb < 4; ++nb) {
            int n = warp_n*32 + nb*8 + qid*2;
            float2 bb = *(const float2*)&bias[n];
            #pragma unroll
            for (int half = 0; half < 2; ++half) {
                int m = warp_m*64 + mb*16 + gid + half*8;
                int hrow = m >> 6, w = m & 63;
                size_t pos = ((size_t)((d0*G + h0 + hrow)*G + w))*64 + n;
                float v0 = fmaxf(acc[mb][nb][half*2+0] + bb.x, 0.f);
                float v1 = fmaxf(acc[mb][nb][half*2+1] + bb.y, 0.f);
                if (SPLIT_OUT) {
                    unsigned hp, lp;
                    split_pack2(v0, v1, hp, lp);
                    *(unsigned*)(outH + pos) = hp;
                    *(unsigned*)(outL + pos) = lp;
                } else {
                    *(float2*)(outF + pos) = make_float2(v0, v1);
                }
            }
        }
}

// ---------------- launch -----------------------------------------------------
extern "C" void kernel_launch(void* const* d_in, const int* in_sizes, int n_in,
                              void* d_out, int out_size)
{
    const float* pos = (const float*)d_in[0];
    const int*   pts = (const int*)d_in[1];
    const float* W1  = (const float*)d_in[2];
    const float* b1  = (const float*)d_in[3];
    const float* W2  = (const float*)d_in[4];
    const float* b2  = (const float*)d_in[5];
    const float* Wk1 = (const float*)d_in[6];
    const float* bk1 = (const float*)d_in[7];
    const float* Wk2 = (const float*)d_in[8];
    const float* bk2 = (const float*)d_in[9];
    const float* Cw1 = (const float*)d_in[10];
    const float* Cb1 = (const float*)d_in[11];
    const float* Cw2 = (const float*)d_in[12];
    const float* Cb2 = (const float*)d_in[13];
    float* out = (float*)d_out;

    void *pSums, *pCnt, *pYh, *pYl, *pWf1, *pWf2;
    cudaGetSymbolAddress(&pSums, g_sums);
    cudaGetSymbolAddress(&pCnt,  g_cnt);
    cudaGetSymbolAddress(&pYh,   g_yh);
    cudaGetSymbolAddress(&pYl,   g_yl);
    cudaGetSymbolAddress(&pWf1,  g_wf1);
    cudaGetSymbolAddress(&pWf2,  g_wf2);

    cudaFuncSetAttribute(mlp_tc, cudaFuncAttributeMaxDynamicSharedMemorySize, MLP_SMEM);
    cudaFuncSetAttribute(conv_mma<true,true>,   cudaFuncAttributeMaxDynamicSharedMemorySize, CONV_SMEM);
    cudaFuncSetAttribute(conv_mma<false,false>, cudaFuncAttributeMaxDynamicSharedMemorySize, CONV_SMEM);

    cudaMemsetAsync(pSums, 0, sizeof(float) * (size_t)S * L);
    cudaMemsetAsync(pCnt,  0, sizeof(float) * (size_t)S);

    repack_all<<<232, 256>>>(Cw1, Cw2, W2);
    mlp_tc<<<NPTS/16, 256, MLP_SMEM>>>(pos, pts, W1, b1, b2, Wk1, bk1, Wk2, bk2);
    conv_mma<true,true><<<2048, 128, CONV_SMEM>>>(
        nullptr, nullptr, (const float*)pSums, (const float*)pCnt,
        (const uint4*)pWf1, Cb1,
        nullptr, (__nv_bfloat16*)pYh, (__nv_bfloat16*)pYl);
    conv_mma<false,false><<<2048, 128, CONV_SMEM>>>(
        (const __nv_bfloat16*)pYh, (const __nv_bfloat16*)pYl, nullptr, nullptr,
        (const uint4*)pWf2, Cb2,
        out, nullptr, nullptr);
}